// round 1
// baseline (speedup 1.0000x reference)
#include <cuda_runtime.h>
#include <math.h>

// Problem constants
#define TT 8192      // tokens = B*S
#define HD 1024      // hidden
#define ID 2752      // intermediate
#define ED 8         // experts
#define KD 2         // top-k

// ---------------- device scratch (static allocation, allowed) ----------------
__device__ int   g_cnt[ED];
__device__ int   g_tok[ED][TT];            // token index per expert row
__device__ int   g_slot[ED][TT];           // output slot (= 2*t + k) per expert row
__device__ float g_wslot[TT * KD];         // combine weight per slot
__device__ float g_act[(size_t)TT * KD * ID];   // routed activations, row = slot   (~180MB)
__device__ float g_sact[(size_t)TT * ID];       // shared-expert activations        (~90MB)
__device__ float g_outk[(size_t)TT * KD * HD];  // routed expert outputs, row = slot (~64MB)

// ---------------- kernels ----------------

__global__ void zero_cnt_kernel() {
    if (threadIdx.x < ED) g_cnt[threadIdx.x] = 0;
}

// One warp per token: logits -> softmax -> top2 -> renorm -> scatter into lists.
__global__ void gate_kernel(const float* __restrict__ x,
                            const float* __restrict__ gw) {
    int warp = (blockIdx.x * blockDim.x + threadIdx.x) >> 5;
    int lane = threadIdx.x & 31;
    if (warp >= TT) return;
    const float* xr = x + (size_t)warp * HD;

    float acc[ED];
#pragma unroll
    for (int e = 0; e < ED; e++) acc[e] = 0.f;

    for (int h = lane; h < HD; h += 32) {
        float xv = xr[h];
#pragma unroll
        for (int e = 0; e < ED; e++) acc[e] += xv * gw[e * HD + h];
    }
#pragma unroll
    for (int off = 16; off > 0; off >>= 1) {
#pragma unroll
        for (int e = 0; e < ED; e++)
            acc[e] += __shfl_xor_sync(0xFFFFFFFFu, acc[e], off);
    }
    if (lane == 0) {
        float m = acc[0];
#pragma unroll
        for (int e = 1; e < ED; e++) m = fmaxf(m, acc[e]);
        float ex[ED], s = 0.f;
#pragma unroll
        for (int e = 0; e < ED; e++) { ex[e] = expf(acc[e] - m); s += ex[e]; }
        // top-2 (ties: lowest index first, matching jax top_k)
        int i0 = 0;
#pragma unroll
        for (int e = 1; e < ED; e++) if (ex[e] > ex[i0]) i0 = e;
        int i1 = -1;
#pragma unroll
        for (int e = 0; e < ED; e++) {
            if (e == i0) continue;
            if (i1 < 0 || ex[e] > ex[i1]) i1 = e;
        }
        float p0 = ex[i0] / s, p1 = ex[i1] / s;
        float d  = p0 + p1 + 1e-20f;
        float w0 = p0 / d, w1 = p1 / d;

        int t = warp;
        int pos0 = atomicAdd(&g_cnt[i0], 1);
        g_tok[i0][pos0]  = t;
        g_slot[i0][pos0] = 2 * t;
        int pos1 = atomicAdd(&g_cnt[i1], 1);
        g_tok[i1][pos1]  = t;
        g_slot[i1][pos1] = 2 * t + 1;
        g_wslot[2 * t]     = w0;
        g_wslot[2 * t + 1] = w1;
    }
}

// Fused gate+up GEMM with SiLU epilogue.
// C_g = X_gathered @ Wg, C_u = X_gathered @ Wu, act = silu(C_g)*C_u
// BM=BN=64, BK=16, 256 threads, 4x4 (x2 matrices) per thread.
__global__ __launch_bounds__(256)
void gemm1_kernel(const float* __restrict__ X,
                  const float* __restrict__ Wg_base,
                  const float* __restrict__ Wu_base,
                  float* __restrict__ Act,
                  int routed) {
    int e = blockIdx.z;
    int n;
    const float* Wg;
    const float* Wu;
    if (routed) {
        n  = g_cnt[e];
        Wg = Wg_base + (size_t)e * HD * ID;
        Wu = Wu_base + (size_t)e * HD * ID;
    } else {
        n  = TT;
        Wg = Wg_base;
        Wu = Wu_base;
    }
    int row0 = blockIdx.y * 64;
    if (row0 >= n) return;
    int col0 = blockIdx.x * 64;

    __shared__ float As[16][68];
    __shared__ float Bgs[16][64];
    __shared__ float Bus[16][64];
    __shared__ int   s_tok[64];
    __shared__ int   s_orow[64];

    int tid = threadIdx.x;
    if (tid < 64) {
        int r = row0 + tid;
        int t, o;
        if (routed) {
            t = (r < n) ? g_tok[e][r]  : 0;
            o = (r < n) ? g_slot[e][r] : 0;
        } else {
            t = (r < n) ? r : 0;
            o = t;
        }
        s_tok[tid]  = t;
        s_orow[tid] = o;
    }
    __syncthreads();

    float accg[4][4], accu[4][4];
#pragma unroll
    for (int i = 0; i < 4; i++)
#pragma unroll
        for (int j = 0; j < 4; j++) { accg[i][j] = 0.f; accu[i][j] = 0.f; }

    int tx = tid & 15, ty = tid >> 4;
    int lr = tid >> 2, lk = (tid & 3) * 4;     // A load: row, k-offset
    int br = tid >> 4, bc = (tid & 15) * 4;    // B load: k-row, col

    for (int k0 = 0; k0 < HD; k0 += 16) {
        float4 av = *(const float4*)(X + (size_t)s_tok[lr] * HD + k0 + lk);
        As[lk + 0][lr] = av.x;
        As[lk + 1][lr] = av.y;
        As[lk + 2][lr] = av.z;
        As[lk + 3][lr] = av.w;
        *(float4*)&Bgs[br][bc] = *(const float4*)(Wg + (size_t)(k0 + br) * ID + col0 + bc);
        *(float4*)&Bus[br][bc] = *(const float4*)(Wu + (size_t)(k0 + br) * ID + col0 + bc);
        __syncthreads();
#pragma unroll
        for (int kk = 0; kk < 16; kk++) {
            float4 a = *(const float4*)&As[kk][ty * 4];
            float4 g = *(const float4*)&Bgs[kk][tx * 4];
            float4 u = *(const float4*)&Bus[kk][tx * 4];
            float af[4] = {a.x, a.y, a.z, a.w};
            float gf[4] = {g.x, g.y, g.z, g.w};
            float uf[4] = {u.x, u.y, u.z, u.w};
#pragma unroll
            for (int i = 0; i < 4; i++)
#pragma unroll
                for (int j = 0; j < 4; j++) {
                    accg[i][j] = fmaf(af[i], gf[j], accg[i][j]);
                    accu[i][j] = fmaf(af[i], uf[j], accu[i][j]);
                }
        }
        __syncthreads();
    }

#pragma unroll
    for (int i = 0; i < 4; i++) {
        int r = ty * 4 + i;
        if (row0 + r < n) {
            int orow = s_orow[r];
            float* dst = Act + (size_t)orow * ID + col0 + tx * 4;
#pragma unroll
            for (int j = 0; j < 4; j++) {
                float g = accg[i][j];
                float u = accu[i][j];
                float s = g / (1.f + expf(-g));   // silu
                dst[j] = s * u;
            }
        }
    }
}

// Down GEMM: Out[row] = Act[row] @ Wd.  Rows indexed by slot (routed) or token (shared).
__global__ __launch_bounds__(256)
void gemm2_kernel(const float* __restrict__ Act,
                  const float* __restrict__ Wd_base,
                  float* __restrict__ Out,
                  int routed) {
    int e = blockIdx.z;
    int n;
    const float* Wd;
    if (routed) {
        n  = g_cnt[e];
        Wd = Wd_base + (size_t)e * ID * HD;
    } else {
        n  = TT;
        Wd = Wd_base;
    }
    int row0 = blockIdx.y * 64;
    if (row0 >= n) return;
    int col0 = blockIdx.x * 64;

    __shared__ float As[16][68];
    __shared__ float Bs[16][64];
    __shared__ int   s_arow[64];

    int tid = threadIdx.x;
    if (tid < 64) {
        int r = row0 + tid;
        int a;
        if (routed) a = (r < n) ? g_slot[e][r] : 0;
        else        a = (r < n) ? r : 0;
        s_arow[tid] = a;
    }
    __syncthreads();

    float acc[4][4];
#pragma unroll
    for (int i = 0; i < 4; i++)
#pragma unroll
        for (int j = 0; j < 4; j++) acc[i][j] = 0.f;

    int tx = tid & 15, ty = tid >> 4;
    int lr = tid >> 2, lk = (tid & 3) * 4;
    int br = tid >> 4, bc = (tid & 15) * 4;

    for (int k0 = 0; k0 < ID; k0 += 16) {
        float4 av = *(const float4*)(Act + (size_t)s_arow[lr] * ID + k0 + lk);
        As[lk + 0][lr] = av.x;
        As[lk + 1][lr] = av.y;
        As[lk + 2][lr] = av.z;
        As[lk + 3][lr] = av.w;
        *(float4*)&Bs[br][bc] = *(const float4*)(Wd + (size_t)(k0 + br) * HD + col0 + bc);
        __syncthreads();
#pragma unroll
        for (int kk = 0; kk < 16; kk++) {
            float4 a = *(const float4*)&As[kk][ty * 4];
            float4 b = *(const float4*)&Bs[kk][tx * 4];
            float af[4] = {a.x, a.y, a.z, a.w};
            float bf[4] = {b.x, b.y, b.z, b.w};
#pragma unroll
            for (int i = 0; i < 4; i++)
#pragma unroll
                for (int j = 0; j < 4; j++)
                    acc[i][j] = fmaf(af[i], bf[j], acc[i][j]);
        }
        __syncthreads();
    }

#pragma unroll
    for (int i = 0; i < 4; i++) {
        int r = ty * 4 + i;
        if (row0 + r < n) {
            int orow = s_arow[r];
            float* dst = Out + (size_t)orow * HD + col0 + tx * 4;
#pragma unroll
            for (int j = 0; j < 4; j++) dst[j] = acc[i][j];
        }
    }
}

// out[t][h] += w0*outk[2t][h] + w1*outk[2t+1][h]   (out already holds shared expert)
__global__ void combine_kernel(float* __restrict__ out) {
    int t = blockIdx.x;
    int h = threadIdx.x;
    float w0 = g_wslot[2 * t];
    float w1 = g_wslot[2 * t + 1];
    size_t base = (size_t)(2 * t) * HD + h;
    float v = out[(size_t)t * HD + h];
    v += w0 * g_outk[base] + w1 * g_outk[base + HD];
    out[(size_t)t * HD + h] = v;
}

// ---------------- launch ----------------
extern "C" void kernel_launch(void* const* d_in, const int* in_sizes, int n_in,
                              void* d_out, int out_size) {
    const float* x    = (const float*)d_in[0];   // [T, H]
    const float* gw   = (const float*)d_in[1];   // [E, H]
    const float* wg   = (const float*)d_in[2];   // [E, H, I]
    const float* wu   = (const float*)d_in[3];   // [E, H, I]
    const float* wd   = (const float*)d_in[4];   // [E, I, H]
    const float* sg   = (const float*)d_in[5];   // [H, I]
    const float* su   = (const float*)d_in[6];   // [H, I]
    const float* sd   = (const float*)d_in[7];   // [I, H]
    float* out = (float*)d_out;

    zero_cnt_kernel<<<1, 32>>>();
    gate_kernel<<<TT / 8, 256>>>(x, gw);   // 8 warps/block, 1 warp/token

    // routed experts: fused gate+up+silu, then down
    {
        float* act;  cudaGetSymbolAddress((void**)&act,  g_act);
        float* outk; cudaGetSymbolAddress((void**)&outk, g_outk);
        dim3 g1(ID / 64, TT / 64, ED);     // (43, 128, 8)
        gemm1_kernel<<<g1, 256>>>(x, wg, wu, act, 1);
        dim3 g2(HD / 64, TT / 64, ED);     // (16, 128, 8)
        gemm2_kernel<<<g2, 256>>>(act, wd, outk, 1);
    }
    // shared expert: writes d_out directly
    {
        float* sact; cudaGetSymbolAddress((void**)&sact, g_sact);
        dim3 g1(ID / 64, TT / 64, 1);
        gemm1_kernel<<<g1, 256>>>(x, sg, su, sact, 0);
        dim3 g2(HD / 64, TT / 64, 1);
        gemm2_kernel<<<g2, 256>>>(sact, sd, out, 0);
    }
    combine_kernel<<<TT, HD>>>(out);
}

// round 3
// speedup vs baseline: 1.7943x; 1.7943x over previous
#include <cuda_runtime.h>
#include <math.h>
#include <stdint.h>

#define TT 8192      // tokens = B*S
#define HD 1024      // hidden
#define ID 2752      // intermediate
#define ED 8         // experts
#define KD 2         // top-k

// ---------------- device scratch ----------------
__device__ int   g_cnt[ED];
__device__ int   g_tok[ED][TT];
__device__ int   g_slot[ED][TT];
__device__ float g_wslot[TT * KD];
__device__ float g_act[(size_t)TT * KD * ID];   // routed activations (slot-major)
__device__ float g_sact[(size_t)TT * ID];       // shared-expert activations
__device__ float g_outk[(size_t)TT * KD * HD];  // routed outputs (slot-major)

// ---------------- helpers ----------------
__device__ __forceinline__ uint32_t smem_u32(const void* p) {
    uint32_t a;
    asm("{ .reg .u64 t; cvta.to.shared.u64 t, %1; cvt.u32.u64 %0, t; }" : "=r"(a) : "l"(p));
    return a;
}
__device__ __forceinline__ uint32_t to_tf32(float x) {
    uint32_t u;
    asm("cvt.rna.tf32.f32 %0, %1;" : "=r"(u) : "f"(x));
    return u;
}

#define LDSM_X4(r0, r1, r2, r3, addr) \
    asm volatile("ldmatrix.sync.aligned.m8n8.x4.shared.b16 {%0,%1,%2,%3}, [%4];" \
                 : "=r"(r0), "=r"(r1), "=r"(r2), "=r"(r3) : "r"(addr))

#define MMA8(c, a, b0, b1) \
    asm volatile("mma.sync.aligned.m16n8k8.row.col.f32.tf32.tf32.f32 " \
                 "{%0,%1,%2,%3}, {%4,%5,%6,%7}, {%8,%9}, {%0,%1,%2,%3};" \
                 : "+f"((c)[0]), "+f"((c)[1]), "+f"((c)[2]), "+f"((c)[3]) \
                 : "r"((a)[0]), "r"((a)[1]), "r"((a)[2]), "r"((a)[3]), "r"(b0), "r"(b1))

#define STS128(addr, r0, r1, r2, r3) \
    asm volatile("st.shared.v4.b32 [%0], {%1,%2,%3,%4};" :: "r"(addr), "r"(r0), "r"(r1), "r"(r2), "r"(r3) : "memory")
#define STS32(addr, r0) \
    asm volatile("st.shared.b32 [%0], %1;" :: "r"(addr), "r"(r0) : "memory")

// ---------------- small kernels ----------------
__global__ void zero_cnt_kernel() {
    if (threadIdx.x < ED) g_cnt[threadIdx.x] = 0;
}

__global__ void gate_kernel(const float* __restrict__ x,
                            const float* __restrict__ gw) {
    int warp = (blockIdx.x * blockDim.x + threadIdx.x) >> 5;
    int lane = threadIdx.x & 31;
    if (warp >= TT) return;
    const float* xr = x + (size_t)warp * HD;

    float acc[ED];
#pragma unroll
    for (int e = 0; e < ED; e++) acc[e] = 0.f;
    for (int h = lane; h < HD; h += 32) {
        float xv = xr[h];
#pragma unroll
        for (int e = 0; e < ED; e++) acc[e] += xv * gw[e * HD + h];
    }
#pragma unroll
    for (int off = 16; off > 0; off >>= 1) {
#pragma unroll
        for (int e = 0; e < ED; e++)
            acc[e] += __shfl_xor_sync(0xFFFFFFFFu, acc[e], off);
    }
    if (lane == 0) {
        float m = acc[0];
#pragma unroll
        for (int e = 1; e < ED; e++) m = fmaxf(m, acc[e]);
        float ex[ED], s = 0.f;
#pragma unroll
        for (int e = 0; e < ED; e++) { ex[e] = expf(acc[e] - m); s += ex[e]; }
        int i0 = 0;
#pragma unroll
        for (int e = 1; e < ED; e++) if (ex[e] > ex[i0]) i0 = e;
        int i1 = -1;
#pragma unroll
        for (int e = 0; e < ED; e++) {
            if (e == i0) continue;
            if (i1 < 0 || ex[e] > ex[i1]) i1 = e;
        }
        float p0 = ex[i0] / s, p1 = ex[i1] / s;
        float d  = p0 + p1 + 1e-20f;
        int t = warp;
        int pos0 = atomicAdd(&g_cnt[i0], 1);
        g_tok[i0][pos0]  = t;
        g_slot[i0][pos0] = 2 * t;
        int pos1 = atomicAdd(&g_cnt[i1], 1);
        g_tok[i1][pos1]  = t;
        g_slot[i1][pos1] = 2 * t + 1;
        g_wslot[2 * t]     = p0 / d;
        g_wslot[2 * t + 1] = p1 / d;
    }
}

// ---------------- GEMM 1: act = silu(X@Wg) * (X@Wu) ----------------
// BM=128, BN=64, BK=32. 256 threads = 8 warps (4 M x 2 N), warp tile 32x32 per matrix.
// smem stage: As 16KB + Bg 8KB + Bu 8KB = 32KB, double buffered (64KB).
__global__ __launch_bounds__(256, 1)
void gemm1_mma(const float* __restrict__ X,
               const float* __restrict__ Wg_base,
               const float* __restrict__ Wu_base,
               float* __restrict__ Act,
               int routed) {
    int e = blockIdx.z;
    int n; const float *Wg, *Wu;
    if (routed) { n = g_cnt[e]; Wg = Wg_base + (size_t)e * HD * ID; Wu = Wu_base + (size_t)e * HD * ID; }
    else        { n = TT;       Wg = Wg_base;                        Wu = Wu_base; }
    int row0 = blockIdx.y * 128;
    if (row0 >= n) return;
    int col0 = blockIdx.x * 64;

    extern __shared__ __align__(16) char dyn[];
    uint32_t smem = smem_u32(dyn);
    __shared__ int s_tok[128], s_orow[128];

    int tid = threadIdx.x;
    if (tid < 128) {
        int r = row0 + tid;
        int t, o;
        if (routed) { t = (r < n) ? g_tok[e][r] : g_tok[e][0];
                      o = (r < n) ? g_slot[e][r] : 0; }
        else        { t = (r < n) ? r : 0; o = t; }
        s_tok[tid] = t; s_orow[tid] = o;
    }
    __syncthreads();

    int w = tid >> 5, lane = tid & 31;
    int wm = (w >> 1) * 32, wn = (w & 1) * 32;
    int gi = lane >> 2, tig = lane & 3;

    float cg[2][4][4], cu[2][4][4];
#pragma unroll
    for (int mt = 0; mt < 2; mt++)
#pragma unroll
        for (int nt = 0; nt < 4; nt++)
#pragma unroll
            for (int i = 0; i < 4; i++) { cg[mt][nt][i] = 0.f; cu[mt][nt][i] = 0.f; }

    uint32_t av[4][4], gv[2][4], uv[2][4];

    auto ldA = [&](int k0) {
#pragma unroll
        for (int it = 0; it < 4; it++) {
            int i = tid + it * 256; int r = i >> 3, q = i & 7;
            float4 v = *(const float4*)(X + (size_t)s_tok[r] * HD + k0 + q * 4);
            av[it][0] = to_tf32(v.x); av[it][1] = to_tf32(v.y);
            av[it][2] = to_tf32(v.z); av[it][3] = to_tf32(v.w);
        }
    };
    auto ldB = [&](int k0) {
#pragma unroll
        for (int it = 0; it < 2; it++) {
            int i = tid + it * 256; int k = i & 31, nq = i >> 5;
            float4 vg = *(const float4*)(Wg + (size_t)(k0 + k) * ID + col0 + nq * 4);
            float4 vu = *(const float4*)(Wu + (size_t)(k0 + k) * ID + col0 + nq * 4);
            gv[it][0] = to_tf32(vg.x); gv[it][1] = to_tf32(vg.y);
            gv[it][2] = to_tf32(vg.z); gv[it][3] = to_tf32(vg.w);
            uv[it][0] = to_tf32(vu.x); uv[it][1] = to_tf32(vu.y);
            uv[it][2] = to_tf32(vu.z); uv[it][3] = to_tf32(vu.w);
        }
    };
    auto stage = [&](uint32_t base) {
        uint32_t As = base, Bg_s = base + 16384, Bu_s = base + 24576;
#pragma unroll
        for (int it = 0; it < 4; it++) {
            int i = tid + it * 256; int r = i >> 3, q = i & 7;
            uint32_t ad = As + r * 128 + ((q ^ (r & 7)) << 4);
            STS128(ad, av[it][0], av[it][1], av[it][2], av[it][3]);
        }
#pragma unroll
        for (int it = 0; it < 2; it++) {
            int i = tid + it * 256; int k = i & 31, nq = i >> 5;
#pragma unroll
            for (int j = 0; j < 4; j++) {
                int nn = nq * 4 + j;
                uint32_t off = nn * 128 + (((k >> 2) ^ (nn & 7)) << 4) + (k & 3) * 4;
                STS32(Bg_s + off, gv[it][j]);
                STS32(Bu_s + off, uv[it][j]);
            }
        }
    };
    auto compute = [&](uint32_t base) {
        uint32_t As = base, Bg_s = base + 16384, Bu_s = base + 24576;
        uint32_t bg[4][4], bu[4][4];
#pragma unroll
        for (int ks = 0; ks < 4; ks++) {
            if ((ks & 1) == 0) {
#pragma unroll
                for (int nt = 0; nt < 4; nt++) {
                    int row = wn + nt * 8 + (lane & 7);
                    int gr = ks * 2 + (lane >> 3);
                    uint32_t off = row * 128 + ((gr ^ (row & 7)) << 4);
                    LDSM_X4(bg[nt][0], bg[nt][1], bg[nt][2], bg[nt][3], Bg_s + off);
                    LDSM_X4(bu[nt][0], bu[nt][1], bu[nt][2], bu[nt][3], Bu_s + off);
                }
            }
            uint32_t a[2][4];
#pragma unroll
            for (int mt = 0; mt < 2; mt++) {
                int row = wm + mt * 16 + (lane & 7) + ((lane >> 3) & 1) * 8;
                int gr = ks * 2 + (lane >> 4);
                uint32_t off = row * 128 + ((gr ^ (row & 7)) << 4);
                LDSM_X4(a[mt][0], a[mt][1], a[mt][2], a[mt][3], As + off);
            }
            int o = (ks & 1) * 2;
#pragma unroll
            for (int mt = 0; mt < 2; mt++)
#pragma unroll
                for (int nt = 0; nt < 4; nt++) {
                    MMA8(cg[mt][nt], a[mt], bg[nt][o], bg[nt][o + 1]);
                    MMA8(cu[mt][nt], a[mt], bu[nt][o], bu[nt][o + 1]);
                }
        }
    };

    const int NCH = HD / 32;  // 32
    ldA(0); ldB(0);
    stage(smem);
    __syncthreads();
    for (int c = 0; c < NCH; c++) {
        uint32_t base = smem + (c & 1) * 32768;
        if (c + 1 < NCH) { ldA((c + 1) * 32); ldB((c + 1) * 32); }
        compute(base);
        __syncthreads();
        if (c + 1 < NCH) {
            stage(smem + ((c + 1) & 1) * 32768);
        }
        __syncthreads();
    }

    // epilogue: silu(g)*u, float2 stores to gathered rows
#pragma unroll
    for (int mt = 0; mt < 2; mt++)
#pragma unroll
        for (int nt = 0; nt < 4; nt++) {
            int col = col0 + wn + nt * 8 + tig * 2;
#pragma unroll
            for (int h = 0; h < 2; h++) {
                int lr = wm + mt * 16 + gi + h * 8;
                if (row0 + lr < n) {
                    float g0 = cg[mt][nt][h * 2], g1 = cg[mt][nt][h * 2 + 1];
                    float u0 = cu[mt][nt][h * 2], u1 = cu[mt][nt][h * 2 + 1];
                    float2 o;
                    o.x = g0 / (1.f + expf(-g0)) * u0;
                    o.y = g1 / (1.f + expf(-g1)) * u1;
                    *(float2*)(Act + (size_t)s_orow[lr] * ID + col) = o;
                }
            }
        }
}

// ---------------- GEMM 2: Out = Act @ Wd ----------------
// BM=128, BN=128, BK=32. 8 warps (2 M x 4 N), warp tile 64x32.
// smem stage: As 16KB + Bs 16KB = 32KB, double buffered (64KB).
__global__ __launch_bounds__(256, 1)
void gemm2_mma(const float* __restrict__ ActBase,
               const float* __restrict__ Wd_base,
               float* __restrict__ Out,
               int routed) {
    int e = blockIdx.z;
    int n; const float* Wd;
    if (routed) { n = g_cnt[e]; Wd = Wd_base + (size_t)e * ID * HD; }
    else        { n = TT;       Wd = Wd_base; }
    int row0 = blockIdx.y * 128;
    if (row0 >= n) return;
    int col0 = blockIdx.x * 128;

    extern __shared__ __align__(16) char dyn[];
    uint32_t smem = smem_u32(dyn);
    __shared__ int s_row[128];

    int tid = threadIdx.x;
    if (tid < 128) {
        int r = row0 + tid;
        int a;
        if (routed) a = (r < n) ? g_slot[e][r] : 0;
        else        a = (r < n) ? r : 0;
        s_row[tid] = a;
    }
    __syncthreads();

    int w = tid >> 5, lane = tid & 31;
    int wm = (w >> 2) * 64, wn = (w & 3) * 32;
    int gi = lane >> 2, tig = lane & 3;

    float cc[4][4][4];
#pragma unroll
    for (int mt = 0; mt < 4; mt++)
#pragma unroll
        for (int nt = 0; nt < 4; nt++)
#pragma unroll
            for (int i = 0; i < 4; i++) cc[mt][nt][i] = 0.f;

    uint32_t av[4][4], bv[4][4];

    auto ldA = [&](int k0) {
#pragma unroll
        for (int it = 0; it < 4; it++) {
            int i = tid + it * 256; int r = i >> 3, q = i & 7;
            float4 v = *(const float4*)(ActBase + (size_t)s_row[r] * ID + k0 + q * 4);
            av[it][0] = to_tf32(v.x); av[it][1] = to_tf32(v.y);
            av[it][2] = to_tf32(v.z); av[it][3] = to_tf32(v.w);
        }
    };
    auto ldB = [&](int k0) {
#pragma unroll
        for (int it = 0; it < 4; it++) {
            int i = tid + it * 256; int k = i & 31, nq = i >> 5;
            float4 v = *(const float4*)(Wd + (size_t)(k0 + k) * HD + col0 + nq * 4);
            bv[it][0] = to_tf32(v.x); bv[it][1] = to_tf32(v.y);
            bv[it][2] = to_tf32(v.z); bv[it][3] = to_tf32(v.w);
        }
    };
    auto stage = [&](uint32_t base) {
        uint32_t As = base, Bs = base + 16384;
#pragma unroll
        for (int it = 0; it < 4; it++) {
            int i = tid + it * 256; int r = i >> 3, q = i & 7;
            uint32_t ad = As + r * 128 + ((q ^ (r & 7)) << 4);
            STS128(ad, av[it][0], av[it][1], av[it][2], av[it][3]);
        }
#pragma unroll
        for (int it = 0; it < 4; it++) {
            int i = tid + it * 256; int k = i & 31, nq = i >> 5;
#pragma unroll
            for (int j = 0; j < 4; j++) {
                int nn = nq * 4 + j;
                uint32_t off = nn * 128 + (((k >> 2) ^ (nn & 7)) << 4) + (k & 3) * 4;
                STS32(Bs + off, bv[it][j]);
            }
        }
    };
    auto compute = [&](uint32_t base) {
        uint32_t As = base, Bs = base + 16384;
        uint32_t b[4][4];
#pragma unroll
        for (int ks = 0; ks < 4; ks++) {
            if ((ks & 1) == 0) {
#pragma unroll
                for (int nt = 0; nt < 4; nt++) {
                    int row = wn + nt * 8 + (lane & 7);
                    int gr = ks * 2 + (lane >> 3);
                    uint32_t off = row * 128 + ((gr ^ (row & 7)) << 4);
                    LDSM_X4(b[nt][0], b[nt][1], b[nt][2], b[nt][3], Bs + off);
                }
            }
            uint32_t a[4][4];
#pragma unroll
            for (int mt = 0; mt < 4; mt++) {
                int row = wm + mt * 16 + (lane & 7) + ((lane >> 3) & 1) * 8;
                int gr = ks * 2 + (lane >> 4);
                uint32_t off = row * 128 + ((gr ^ (row & 7)) << 4);
                LDSM_X4(a[mt][0], a[mt][1], a[mt][2], a[mt][3], As + off);
            }
            int o = (ks & 1) * 2;
#pragma unroll
            for (int mt = 0; mt < 4; mt++)
#pragma unroll
                for (int nt = 0; nt < 4; nt++)
                    MMA8(cc[mt][nt], a[mt], b[nt][o], b[nt][o + 1]);
        }
    };

    const int NCH = ID / 32;  // 86
    ldA(0); ldB(0);
    stage(smem);
    __syncthreads();
    for (int c = 0; c < NCH; c++) {
        uint32_t base = smem + (c & 1) * 32768;
        if (c + 1 < NCH) { ldA((c + 1) * 32); ldB((c + 1) * 32); }
        compute(base);
        __syncthreads();
        if (c + 1 < NCH) {
            stage(smem + ((c + 1) & 1) * 32768);
        }
        __syncthreads();
    }

#pragma unroll
    for (int mt = 0; mt < 4; mt++)
#pragma unroll
        for (int nt = 0; nt < 4; nt++) {
            int col = col0 + wn + nt * 8 + tig * 2;
#pragma unroll
            for (int h = 0; h < 2; h++) {
                int lr = wm + mt * 16 + gi + h * 8;
                if (row0 + lr < n) {
                    float2 o;
                    o.x = cc[mt][nt][h * 2];
                    o.y = cc[mt][nt][h * 2 + 1];
                    *(float2*)(Out + (size_t)s_row[lr] * HD + col) = o;
                }
            }
        }
}

// out[t] += w0*outk[2t] + w1*outk[2t+1]
__global__ void combine_kernel(float* __restrict__ out) {
    int t = blockIdx.x;
    int h = threadIdx.x;
    float w0 = g_wslot[2 * t];
    float w1 = g_wslot[2 * t + 1];
    size_t base = (size_t)(2 * t) * HD + h;
    float v = out[(size_t)t * HD + h];
    v += w0 * g_outk[base] + w1 * g_outk[base + HD];
    out[(size_t)t * HD + h] = v;
}

// ---------------- launch ----------------
extern "C" void kernel_launch(void* const* d_in, const int* in_sizes, int n_in,
                              void* d_out, int out_size) {
    const float* x  = (const float*)d_in[0];
    const float* gw = (const float*)d_in[1];
    const float* wg = (const float*)d_in[2];
    const float* wu = (const float*)d_in[3];
    const float* wd = (const float*)d_in[4];
    const float* sg = (const float*)d_in[5];
    const float* su = (const float*)d_in[6];
    const float* sd = (const float*)d_in[7];
    float* out = (float*)d_out;

    const int SMEM_BYTES = 65536;
    cudaFuncSetAttribute(gemm1_mma, cudaFuncAttributeMaxDynamicSharedMemorySize, SMEM_BYTES);
    cudaFuncSetAttribute(gemm2_mma, cudaFuncAttributeMaxDynamicSharedMemorySize, SMEM_BYTES);

    zero_cnt_kernel<<<1, 32>>>();
    gate_kernel<<<TT / 8, 256>>>(x, gw);

    float* act;  cudaGetSymbolAddress((void**)&act,  g_act);
    float* outk; cudaGetSymbolAddress((void**)&outk, g_outk);
    float* sact; cudaGetSymbolAddress((void**)&sact, g_sact);

    // routed experts
    {
        dim3 g1(ID / 64, TT / 128, ED);      // (43, 64, 8)
        gemm1_mma<<<g1, 256, SMEM_BYTES>>>(x, wg, wu, act, 1);
        dim3 g2(HD / 128, TT / 128, ED);     // (8, 64, 8)
        gemm2_mma<<<g2, 256, SMEM_BYTES>>>(act, wd, outk, 1);
    }
    // shared expert (writes d_out directly)
    {
        dim3 g1(ID / 64, TT / 128, 1);
        gemm1_mma<<<g1, 256, SMEM_BYTES>>>(x, sg, su, sact, 0);
        dim3 g2(HD / 128, TT / 128, 1);
        gemm2_mma<<<g2, 256, SMEM_BYTES>>>(sact, sd, out, 0);
    }
    combine_kernel<<<TT, HD>>>(out);
}

// round 4
// speedup vs baseline: 3.2430x; 1.8074x over previous
#include <cuda_runtime.h>
#include <math.h>
#include <stdint.h>

#define TT 8192      // tokens = B*S
#define HD 1024      // hidden
#define ID 2752      // intermediate
#define ED 8         // experts
#define KD 2         // top-k

// ---------------- device scratch ----------------
__device__ int   g_cnt[ED];
__device__ int   g_tok[ED][TT];
__device__ int   g_slot[ED][TT];
__device__ float g_wslot[TT * KD];
__device__ float g_act[(size_t)TT * KD * ID];   // routed activations (slot-major, tf32-rounded)
__device__ float g_sact[(size_t)TT * ID];       // shared-expert activations (tf32-rounded)
__device__ float g_outk[(size_t)TT * KD * HD];  // routed outputs (slot-major)
// tf32-rounded / transposed operands
__device__ float g_xt[(size_t)TT * HD];         // x, tf32-rounded
__device__ float g_wgt[(size_t)ED * HD * ID];   // Wg^T  [E][I][H]
__device__ float g_wut[(size_t)ED * HD * ID];   // Wu^T  [E][I][H]
__device__ float g_wdt[(size_t)ED * ID * HD];   // Wd^T  [E][H][I]
__device__ float g_sgt[(size_t)HD * ID];        // sg^T  [I][H]
__device__ float g_sut[(size_t)HD * ID];        // su^T  [I][H]
__device__ float g_sdt[(size_t)ID * HD];        // sd^T  [H][I]

// ---------------- helpers ----------------
__device__ __forceinline__ uint32_t smem_u32(const void* p) {
    uint32_t a;
    asm("{ .reg .u64 t; cvta.to.shared.u64 t, %1; cvt.u32.u64 %0, t; }" : "=r"(a) : "l"(p));
    return a;
}
__device__ __forceinline__ uint32_t to_tf32(float x) {
    uint32_t u;
    asm("cvt.rna.tf32.f32 %0, %1;" : "=r"(u) : "f"(x));
    return u;
}

#define LDSM_X4(r0, r1, r2, r3, addr) \
    asm volatile("ldmatrix.sync.aligned.m8n8.x4.shared.b16 {%0,%1,%2,%3}, [%4];" \
                 : "=r"(r0), "=r"(r1), "=r"(r2), "=r"(r3) : "r"(addr))

#define MMA8(c, a, b0, b1) \
    asm volatile("mma.sync.aligned.m16n8k8.row.col.f32.tf32.tf32.f32 " \
                 "{%0,%1,%2,%3}, {%4,%5,%6,%7}, {%8,%9}, {%0,%1,%2,%3};" \
                 : "+f"((c)[0]), "+f"((c)[1]), "+f"((c)[2]), "+f"((c)[3]) \
                 : "r"((a)[0]), "r"((a)[1]), "r"((a)[2]), "r"((a)[3]), "r"(b0), "r"(b1))

#define CP_ASYNC16(dst, src) \
    asm volatile("cp.async.cg.shared.global [%0], [%1], 16;" :: "r"(dst), "l"(src) : "memory")
#define CP_COMMIT() asm volatile("cp.async.commit_group;" ::: "memory")
#define CP_WAIT2()  asm volatile("cp.async.wait_group 2;" ::: "memory")

// ---------------- small kernels ----------------
__global__ void zero_cnt_kernel() {
    if (threadIdx.x < ED) g_cnt[threadIdx.x] = 0;
}

__global__ void gate_kernel(const float* __restrict__ x,
                            const float* __restrict__ gw) {
    int warp = (blockIdx.x * blockDim.x + threadIdx.x) >> 5;
    int lane = threadIdx.x & 31;
    if (warp >= TT) return;
    const float* xr = x + (size_t)warp * HD;

    float acc[ED];
#pragma unroll
    for (int e = 0; e < ED; e++) acc[e] = 0.f;
    for (int h = lane; h < HD; h += 32) {
        float xv = xr[h];
#pragma unroll
        for (int e = 0; e < ED; e++) acc[e] += xv * gw[e * HD + h];
    }
#pragma unroll
    for (int off = 16; off > 0; off >>= 1) {
#pragma unroll
        for (int e = 0; e < ED; e++)
            acc[e] += __shfl_xor_sync(0xFFFFFFFFu, acc[e], off);
    }
    if (lane == 0) {
        float m = acc[0];
#pragma unroll
        for (int e = 1; e < ED; e++) m = fmaxf(m, acc[e]);
        float ex[ED], s = 0.f;
#pragma unroll
        for (int e = 0; e < ED; e++) { ex[e] = expf(acc[e] - m); s += ex[e]; }
        int i0 = 0;
#pragma unroll
        for (int e = 1; e < ED; e++) if (ex[e] > ex[i0]) i0 = e;
        int i1 = -1;
#pragma unroll
        for (int e = 0; e < ED; e++) {
            if (e == i0) continue;
            if (i1 < 0 || ex[e] > ex[i1]) i1 = e;
        }
        float p0 = ex[i0] / s, p1 = ex[i1] / s;
        float d  = p0 + p1 + 1e-20f;
        int t = warp;
        int pos0 = atomicAdd(&g_cnt[i0], 1);
        g_tok[i0][pos0]  = t;
        g_slot[i0][pos0] = 2 * t;
        int pos1 = atomicAdd(&g_cnt[i1], 1);
        g_tok[i1][pos1]  = t;
        g_slot[i1][pos1] = 2 * t + 1;
        g_wslot[2 * t]     = p0 / d;
        g_wslot[2 * t + 1] = p1 / d;
    }
}

// x -> tf32-rounded copy
__global__ void convx_kernel(const float* __restrict__ x) {
    size_t i = ((size_t)blockIdx.x * 256 + threadIdx.x) * 4;
    float4 v = *(const float4*)(x + i);
    float4 o;
    o.x = __uint_as_float(to_tf32(v.x));
    o.y = __uint_as_float(to_tf32(v.y));
    o.z = __uint_as_float(to_tf32(v.z));
    o.w = __uint_as_float(to_tf32(v.w));
    *(float4*)(g_xt + i) = o;
}

// src [E][K][N] row-major -> dst [E][N][K] (tf32-rounded)
__global__ void transpose_cvt(const float* __restrict__ src, float* __restrict__ dst,
                              int K, int N) {
    __shared__ float tile[32][33];
    size_t eoff = (size_t)blockIdx.z * K * N;
    src += eoff; dst += eoff;
    int n0 = blockIdx.x * 32, k0 = blockIdx.y * 32;
    int tx = threadIdx.x & 31, ty = threadIdx.x >> 5;  // 256 thr
#pragma unroll
    for (int i = 0; i < 32; i += 8)
        tile[ty + i][tx] = src[(size_t)(k0 + ty + i) * N + n0 + tx];
    __syncthreads();
#pragma unroll
    for (int i = 0; i < 32; i += 8)
        dst[(size_t)(n0 + ty + i) * K + k0 + tx] =
            __uint_as_float(to_tf32(tile[tx][ty + i]));
}

// ---------------- GEMM 1: act = silu(X@Wg) * (X@Wu) ----------------
// BM=128, BN=64, BK=32. 512 threads = 16 warps (4M x 4N); warp tile 32x16 per matrix.
// stage: A 16KB + Bg 8KB + Bu 8KB = 32KB, 4 stages = 128KB.
__global__ __launch_bounds__(512, 1)
void gemm1_mma(const float* __restrict__ Xt,
               const float* __restrict__ Wgt_base,
               const float* __restrict__ Wut_base,
               float* __restrict__ Act,
               int routed) {
    int e = blockIdx.z;
    int n; const float *Wg, *Wu;
    if (routed) { n = g_cnt[e]; Wg = Wgt_base + (size_t)e * HD * ID; Wu = Wut_base + (size_t)e * HD * ID; }
    else        { n = TT;       Wg = Wgt_base;                        Wu = Wut_base; }
    int row0 = blockIdx.y * 128;
    if (row0 >= n) return;
    int col0 = blockIdx.x * 64;

    extern __shared__ __align__(16) char dyn[];
    uint32_t smem = smem_u32(dyn);
    __shared__ int s_tok[128], s_orow[128];

    int tid = threadIdx.x;
    if (tid < 128) {
        int r = row0 + tid;
        int t, o;
        if (routed) { t = (r < n) ? g_tok[e][r] : g_tok[e][0];
                      o = (r < n) ? g_slot[e][r] : 0; }
        else        { t = (r < n) ? r : 0; o = t; }
        s_tok[tid] = t; s_orow[tid] = o;
    }
    __syncthreads();

    int w = tid >> 5, lane = tid & 31;
    int wm = (w >> 2) * 32, wn = (w & 3) * 16;
    int gi = lane >> 2, tig = lane & 3;

    float cg[2][2][4], cu[2][2][4];
#pragma unroll
    for (int mt = 0; mt < 2; mt++)
#pragma unroll
        for (int nt = 0; nt < 2; nt++)
#pragma unroll
            for (int i = 0; i < 4; i++) { cg[mt][nt][i] = 0.f; cu[mt][nt][i] = 0.f; }

    auto issue = [&](int c) {
        uint32_t base = smem + (c & 3) * 32768;
        uint32_t As = base, Bg_s = base + 16384, Bu_s = base + 24576;
        int k0 = c * 32;
#pragma unroll
        for (int it = 0; it < 2; it++) {
            int i = tid + it * 512; int r = i >> 3, q = i & 7;
            uint32_t d = As + r * 128 + ((q ^ (r & 7)) << 4);
            CP_ASYNC16(d, Xt + (size_t)s_tok[r] * HD + k0 + q * 4);
        }
        {
            int nn = tid >> 3, g = tid & 7;
            uint32_t d = nn * 128 + ((g ^ (nn & 7)) << 4);
            const float* gs = Wg + (size_t)(col0 + nn) * HD + k0 + g * 4;
            const float* us = Wu + (size_t)(col0 + nn) * HD + k0 + g * 4;
            CP_ASYNC16(Bg_s + d, gs);
            CP_ASYNC16(Bu_s + d, us);
        }
    };
    auto compute = [&](uint32_t base) {
        uint32_t As = base, Bg_s = base + 16384, Bu_s = base + 24576;
        uint32_t bg[2][4], bu[2][4];
#pragma unroll
        for (int ks = 0; ks < 4; ks++) {
            if ((ks & 1) == 0) {
#pragma unroll
                for (int nt = 0; nt < 2; nt++) {
                    int row = wn + nt * 8 + (lane & 7);
                    int gr = ks * 2 + (lane >> 3);
                    uint32_t off = row * 128 + ((gr ^ (row & 7)) << 4);
                    LDSM_X4(bg[nt][0], bg[nt][1], bg[nt][2], bg[nt][3], Bg_s + off);
                    LDSM_X4(bu[nt][0], bu[nt][1], bu[nt][2], bu[nt][3], Bu_s + off);
                }
            }
            uint32_t a[2][4];
#pragma unroll
            for (int mt = 0; mt < 2; mt++) {
                int row = wm + mt * 16 + (lane & 7) + ((lane >> 3) & 1) * 8;
                int gr = ks * 2 + (lane >> 4);
                uint32_t off = row * 128 + ((gr ^ (row & 7)) << 4);
                LDSM_X4(a[mt][0], a[mt][1], a[mt][2], a[mt][3], As + off);
            }
            int o = (ks & 1) * 2;
#pragma unroll
            for (int mt = 0; mt < 2; mt++)
#pragma unroll
                for (int nt = 0; nt < 2; nt++) {
                    MMA8(cg[mt][nt], a[mt], bg[nt][o], bg[nt][o + 1]);
                    MMA8(cu[mt][nt], a[mt], bu[nt][o], bu[nt][o + 1]);
                }
        }
    };

    const int NCH = HD / 32;  // 32
    issue(0); CP_COMMIT();
    issue(1); CP_COMMIT();
    issue(2); CP_COMMIT();
    for (int c = 0; c < NCH; c++) {
        CP_WAIT2();
        __syncthreads();
        if (c + 3 < NCH) issue(c + 3);
        CP_COMMIT();
        compute(smem + (c & 3) * 32768);
    }

    // epilogue: silu(g)*u, tf32-rounded float2 stores to gathered rows
#pragma unroll
    for (int mt = 0; mt < 2; mt++)
#pragma unroll
        for (int nt = 0; nt < 2; nt++) {
            int col = col0 + wn + nt * 8 + tig * 2;
#pragma unroll
            for (int h = 0; h < 2; h++) {
                int lr = wm + mt * 16 + gi + h * 8;
                if (row0 + lr < n) {
                    float g0 = cg[mt][nt][h * 2], g1 = cg[mt][nt][h * 2 + 1];
                    float u0 = cu[mt][nt][h * 2], u1 = cu[mt][nt][h * 2 + 1];
                    float2 o;
                    o.x = __uint_as_float(to_tf32(g0 / (1.f + expf(-g0)) * u0));
                    o.y = __uint_as_float(to_tf32(g1 / (1.f + expf(-g1)) * u1));
                    *(float2*)(Act + (size_t)s_orow[lr] * ID + col) = o;
                }
            }
        }
}

// ---------------- GEMM 2: Out = Act @ Wd ----------------
// BM=128, BN=128, BK=32. 512 threads = 16 warps (4M x 4N); warp tile 32x32.
// stage: A 16KB + B 16KB = 32KB, 4 stages = 128KB.
__global__ __launch_bounds__(512, 1)
void gemm2_mma(const float* __restrict__ ActBase,
               const float* __restrict__ Wdt_base,
               float* __restrict__ Out,
               int routed) {
    int e = blockIdx.z;
    int n; const float* Wd;
    if (routed) { n = g_cnt[e]; Wd = Wdt_base + (size_t)e * ID * HD; }
    else        { n = TT;       Wd = Wdt_base; }
    int row0 = blockIdx.y * 128;
    if (row0 >= n) return;
    int col0 = blockIdx.x * 128;

    extern __shared__ __align__(16) char dyn[];
    uint32_t smem = smem_u32(dyn);
    __shared__ int s_row[128];

    int tid = threadIdx.x;
    if (tid < 128) {
        int r = row0 + tid;
        int a;
        if (routed) a = (r < n) ? g_slot[e][r] : 0;
        else        a = (r < n) ? r : 0;
        s_row[tid] = a;
    }
    __syncthreads();

    int w = tid >> 5, lane = tid & 31;
    int wm = (w >> 2) * 32, wn = (w & 3) * 32;
    int gi = lane >> 2, tig = lane & 3;

    float cc[2][4][4];
#pragma unroll
    for (int mt = 0; mt < 2; mt++)
#pragma unroll
        for (int nt = 0; nt < 4; nt++)
#pragma unroll
            for (int i = 0; i < 4; i++) cc[mt][nt][i] = 0.f;

    auto issue = [&](int c) {
        uint32_t base = smem + (c & 3) * 32768;
        uint32_t As = base, Bs = base + 16384;
        int k0 = c * 32;
#pragma unroll
        for (int it = 0; it < 2; it++) {
            int i = tid + it * 512; int r = i >> 3, q = i & 7;
            uint32_t d = As + r * 128 + ((q ^ (r & 7)) << 4);
            CP_ASYNC16(d, ActBase + (size_t)s_row[r] * ID + k0 + q * 4);
        }
#pragma unroll
        for (int it = 0; it < 2; it++) {
            int i = tid + it * 512; int nn = i >> 3, g = i & 7;
            uint32_t d = Bs + nn * 128 + ((g ^ (nn & 7)) << 4);
            CP_ASYNC16(d, Wd + (size_t)(col0 + nn) * ID + k0 + g * 4);
        }
    };
    auto compute = [&](uint32_t base) {
        uint32_t As = base, Bs = base + 16384;
        uint32_t b[4][4];
#pragma unroll
        for (int ks = 0; ks < 4; ks++) {
            if ((ks & 1) == 0) {
#pragma unroll
                for (int nt = 0; nt < 4; nt++) {
                    int row = wn + nt * 8 + (lane & 7);
                    int gr = ks * 2 + (lane >> 3);
                    uint32_t off = row * 128 + ((gr ^ (row & 7)) << 4);
                    LDSM_X4(b[nt][0], b[nt][1], b[nt][2], b[nt][3], Bs + off);
                }
            }
            uint32_t a[2][4];
#pragma unroll
            for (int mt = 0; mt < 2; mt++) {
                int row = wm + mt * 16 + (lane & 7) + ((lane >> 3) & 1) * 8;
                int gr = ks * 2 + (lane >> 4);
                uint32_t off = row * 128 + ((gr ^ (row & 7)) << 4);
                LDSM_X4(a[mt][0], a[mt][1], a[mt][2], a[mt][3], As + off);
            }
            int o = (ks & 1) * 2;
#pragma unroll
            for (int mt = 0; mt < 2; mt++)
#pragma unroll
                for (int nt = 0; nt < 4; nt++)
                    MMA8(cc[mt][nt], a[mt], b[nt][o], b[nt][o + 1]);
        }
    };

    const int NCH = ID / 32;  // 86
    issue(0); CP_COMMIT();
    issue(1); CP_COMMIT();
    issue(2); CP_COMMIT();
    for (int c = 0; c < NCH; c++) {
        CP_WAIT2();
        __syncthreads();
        if (c + 3 < NCH) issue(c + 3);
        CP_COMMIT();
        compute(smem + (c & 3) * 32768);
    }

#pragma unroll
    for (int mt = 0; mt < 2; mt++)
#pragma unroll
        for (int nt = 0; nt < 4; nt++) {
            int col = col0 + wn + nt * 8 + tig * 2;
#pragma unroll
            for (int h = 0; h < 2; h++) {
                int lr = wm + mt * 16 + gi + h * 8;
                if (row0 + lr < n) {
                    float2 o;
                    o.x = cc[mt][nt][h * 2];
                    o.y = cc[mt][nt][h * 2 + 1];
                    *(float2*)(Out + (size_t)s_row[lr] * HD + col) = o;
                }
            }
        }
}

// out[t] += w0*outk[2t] + w1*outk[2t+1]
__global__ void combine_kernel(float* __restrict__ out) {
    int t = blockIdx.x;
    int h = threadIdx.x;
    float w0 = g_wslot[2 * t];
    float w1 = g_wslot[2 * t + 1];
    size_t base = (size_t)(2 * t) * HD + h;
    float v = out[(size_t)t * HD + h];
    v += w0 * g_outk[base] + w1 * g_outk[base + HD];
    out[(size_t)t * HD + h] = v;
}

// ---------------- launch ----------------
extern "C" void kernel_launch(void* const* d_in, const int* in_sizes, int n_in,
                              void* d_out, int out_size) {
    const float* x  = (const float*)d_in[0];
    const float* gw = (const float*)d_in[1];
    const float* wg = (const float*)d_in[2];
    const float* wu = (const float*)d_in[3];
    const float* wd = (const float*)d_in[4];
    const float* sg = (const float*)d_in[5];
    const float* su = (const float*)d_in[6];
    const float* sd = (const float*)d_in[7];
    float* out = (float*)d_out;

    const int SMEM_BYTES = 4 * 32768;  // 128KB
    cudaFuncSetAttribute(gemm1_mma, cudaFuncAttributeMaxDynamicSharedMemorySize, SMEM_BYTES);
    cudaFuncSetAttribute(gemm2_mma, cudaFuncAttributeMaxDynamicSharedMemorySize, SMEM_BYTES);

    float* xt;   cudaGetSymbolAddress((void**)&xt,   g_xt);
    float* wgt;  cudaGetSymbolAddress((void**)&wgt,  g_wgt);
    float* wut;  cudaGetSymbolAddress((void**)&wut,  g_wut);
    float* wdt;  cudaGetSymbolAddress((void**)&wdt,  g_wdt);
    float* sgt;  cudaGetSymbolAddress((void**)&sgt,  g_sgt);
    float* sut;  cudaGetSymbolAddress((void**)&sut,  g_sut);
    float* sdt;  cudaGetSymbolAddress((void**)&sdt,  g_sdt);
    float* act;  cudaGetSymbolAddress((void**)&act,  g_act);
    float* outk; cudaGetSymbolAddress((void**)&outk, g_outk);
    float* sact; cudaGetSymbolAddress((void**)&sact, g_sact);

    zero_cnt_kernel<<<1, 32>>>();
    gate_kernel<<<TT / 8, 256>>>(x, gw);

    // pre-pass: tf32 rounding + weight transposes
    convx_kernel<<<TT * HD / 1024, 256>>>(x);
    {
        dim3 gtu(ID / 32, HD / 32, ED);   // [H][I] -> [I][H]
        transpose_cvt<<<gtu, 256>>>(wg, wgt, HD, ID);
        transpose_cvt<<<gtu, 256>>>(wu, wut, HD, ID);
        dim3 gtd(HD / 32, ID / 32, ED);   // [I][H] -> [H][I]
        transpose_cvt<<<gtd, 256>>>(wd, wdt, ID, HD);
        dim3 gsu(ID / 32, HD / 32, 1);
        transpose_cvt<<<gsu, 256>>>(sg, sgt, HD, ID);
        transpose_cvt<<<gsu, 256>>>(su, sut, HD, ID);
        dim3 gsd(HD / 32, ID / 32, 1);
        transpose_cvt<<<gsd, 256>>>(sd, sdt, ID, HD);
    }

    // routed experts
    {
        dim3 g1(ID / 64, TT / 128, ED);      // (43, 64, 8)
        gemm1_mma<<<g1, 512, SMEM_BYTES>>>(xt, wgt, wut, act, 1);
        dim3 g2(HD / 128, TT / 128, ED);     // (8, 64, 8)
        gemm2_mma<<<g2, 512, SMEM_BYTES>>>(act, wdt, outk, 1);
    }
    // shared expert (writes d_out directly)
    {
        dim3 g1(ID / 64, TT / 128, 1);
        gemm1_mma<<<g1, 512, SMEM_BYTES>>>(xt, sgt, sut, sact, 0);
        dim3 g2(HD / 128, TT / 128, 1);
        gemm2_mma<<<g2, 512, SMEM_BYTES>>>(sact, sdt, out, 0);
    }
    combine_kernel<<<TT, HD>>>(out);
}

// round 5
// speedup vs baseline: 3.6285x; 1.1189x over previous
#include <cuda_runtime.h>
#include <math.h>
#include <stdint.h>

#define TT 8192      // tokens = B*S
#define HD 1024      // hidden
#define ID 2752      // intermediate
#define ED 8         // experts
#define KD 2         // top-k

// ---------------- device scratch ----------------
__device__ int   g_cnt[ED];
__device__ int   g_tok[ED][TT];
__device__ int   g_slot[ED][TT];
__device__ float g_wslot[TT * KD];
__device__ float g_act[(size_t)TT * KD * ID];   // routed activations (slot-major, tf32-rounded)
__device__ float g_sact[(size_t)TT * ID];       // shared-expert activations (tf32-rounded)
__device__ float g_outk[(size_t)TT * KD * HD];  // routed outputs (slot-major)
// tf32-rounded / transposed operands
__device__ float g_xt[(size_t)TT * HD];         // x, tf32-rounded
__device__ float g_wgt[(size_t)ED * HD * ID];   // Wg^T  [E][I][H]
__device__ float g_wut[(size_t)ED * HD * ID];   // Wu^T  [E][I][H]
__device__ float g_wdt[(size_t)ED * ID * HD];   // Wd^T  [E][H][I]
__device__ float g_sgt[(size_t)HD * ID];        // sg^T  [I][H]
__device__ float g_sut[(size_t)HD * ID];        // su^T  [I][H]
__device__ float g_sdt[(size_t)ID * HD];        // sd^T  [H][I]

// ---------------- helpers ----------------
__device__ __forceinline__ uint32_t smem_u32(const void* p) {
    uint32_t a;
    asm("{ .reg .u64 t; cvta.to.shared.u64 t, %1; cvt.u32.u64 %0, t; }" : "=r"(a) : "l"(p));
    return a;
}
__device__ __forceinline__ uint32_t to_tf32(float x) {
    uint32_t u;
    asm("cvt.rna.tf32.f32 %0, %1;" : "=r"(u) : "f"(x));
    return u;
}

#define LDSM_X4(r0, r1, r2, r3, addr) \
    asm volatile("ldmatrix.sync.aligned.m8n8.x4.shared.b16 {%0,%1,%2,%3}, [%4];" \
                 : "=r"(r0), "=r"(r1), "=r"(r2), "=r"(r3) : "r"(addr))

#define MMA8(c, a, b0, b1) \
    asm volatile("mma.sync.aligned.m16n8k8.row.col.f32.tf32.tf32.f32 " \
                 "{%0,%1,%2,%3}, {%4,%5,%6,%7}, {%8,%9}, {%0,%1,%2,%3};" \
                 : "+f"((c)[0]), "+f"((c)[1]), "+f"((c)[2]), "+f"((c)[3]) \
                 : "r"((a)[0]), "r"((a)[1]), "r"((a)[2]), "r"((a)[3]), "r"(b0), "r"(b1))

#define CP_ASYNC16(dst, src) \
    asm volatile("cp.async.cg.shared.global [%0], [%1], 16;" :: "r"(dst), "l"(src) : "memory")
#define CP_COMMIT() asm volatile("cp.async.commit_group;" ::: "memory")
#define CP_WAIT2()  asm volatile("cp.async.wait_group 2;" ::: "memory")

#define STAGE1 49152   // gemm1: A 32KB + Bg 8KB + Bu 8KB
#define STAGE2 49152   // gemm2: A 32KB + B 16KB

// ---------------- small kernels ----------------
__global__ void zero_cnt_kernel() {
    if (threadIdx.x < ED) g_cnt[threadIdx.x] = 0;
}

__global__ void gate_kernel(const float* __restrict__ x,
                            const float* __restrict__ gw) {
    int warp = (blockIdx.x * blockDim.x + threadIdx.x) >> 5;
    int lane = threadIdx.x & 31;
    if (warp >= TT) return;
    const float* xr = x + (size_t)warp * HD;

    float acc[ED];
#pragma unroll
    for (int e = 0; e < ED; e++) acc[e] = 0.f;
    for (int h = lane; h < HD; h += 32) {
        float xv = xr[h];
#pragma unroll
        for (int e = 0; e < ED; e++) acc[e] += xv * gw[e * HD + h];
    }
#pragma unroll
    for (int off = 16; off > 0; off >>= 1) {
#pragma unroll
        for (int e = 0; e < ED; e++)
            acc[e] += __shfl_xor_sync(0xFFFFFFFFu, acc[e], off);
    }
    if (lane == 0) {
        float m = acc[0];
#pragma unroll
        for (int e = 1; e < ED; e++) m = fmaxf(m, acc[e]);
        float ex[ED], s = 0.f;
#pragma unroll
        for (int e = 0; e < ED; e++) { ex[e] = expf(acc[e] - m); s += ex[e]; }
        int i0 = 0;
#pragma unroll
        for (int e = 1; e < ED; e++) if (ex[e] > ex[i0]) i0 = e;
        int i1 = -1;
#pragma unroll
        for (int e = 0; e < ED; e++) {
            if (e == i0) continue;
            if (i1 < 0 || ex[e] > ex[i1]) i1 = e;
        }
        float p0 = ex[i0] / s, p1 = ex[i1] / s;
        float d  = p0 + p1 + 1e-20f;
        int t = warp;
        int pos0 = atomicAdd(&g_cnt[i0], 1);
        g_tok[i0][pos0]  = t;
        g_slot[i0][pos0] = 2 * t;
        int pos1 = atomicAdd(&g_cnt[i1], 1);
        g_tok[i1][pos1]  = t;
        g_slot[i1][pos1] = 2 * t + 1;
        g_wslot[2 * t]     = p0 / d;
        g_wslot[2 * t + 1] = p1 / d;
    }
}

// x -> tf32-rounded copy
__global__ void convx_kernel(const float* __restrict__ x) {
    size_t i = ((size_t)blockIdx.x * 256 + threadIdx.x) * 4;
    float4 v = *(const float4*)(x + i);
    float4 o;
    o.x = __uint_as_float(to_tf32(v.x));
    o.y = __uint_as_float(to_tf32(v.y));
    o.z = __uint_as_float(to_tf32(v.z));
    o.w = __uint_as_float(to_tf32(v.w));
    *(float4*)(g_xt + i) = o;
}

// src [E][K][N] row-major -> dst [E][N][K] (tf32-rounded)
__global__ void transpose_cvt(const float* __restrict__ src, float* __restrict__ dst,
                              int K, int N) {
    __shared__ float tile[32][33];
    size_t eoff = (size_t)blockIdx.z * K * N;
    src += eoff; dst += eoff;
    int n0 = blockIdx.x * 32, k0 = blockIdx.y * 32;
    int tx = threadIdx.x & 31, ty = threadIdx.x >> 5;  // 256 thr
#pragma unroll
    for (int i = 0; i < 32; i += 8)
        tile[ty + i][tx] = src[(size_t)(k0 + ty + i) * N + n0 + tx];
    __syncthreads();
#pragma unroll
    for (int i = 0; i < 32; i += 8)
        dst[(size_t)(n0 + ty + i) * K + k0 + tx] =
            __uint_as_float(to_tf32(tile[tx][ty + i]));
}

// ---------------- GEMM 1: act = silu(X@Wg) * (X@Wu) ----------------
// BM=256, BN=64, BK=32. 256 threads = 8 warps (4M x 2N); warp tile 64x32 per matrix.
// z<8: routed expert z; z==8: shared expert.
__global__ __launch_bounds__(256, 1)
void gemm1_mma(const float* __restrict__ Xt,
               const float* __restrict__ Wgt_base,
               const float* __restrict__ Wut_base,
               const float* __restrict__ Sgt,
               const float* __restrict__ Sut,
               float* __restrict__ ActR,
               float* __restrict__ ActS) {
    int e = blockIdx.z;
    int n; const float *Wg, *Wu; float* Act; int routed = (e < ED);
    if (routed) { n = g_cnt[e]; Wg = Wgt_base + (size_t)e * HD * ID; Wu = Wut_base + (size_t)e * HD * ID; Act = ActR; }
    else        { n = TT;       Wg = Sgt;                             Wu = Sut;                             Act = ActS; }
    int row0 = blockIdx.y * 256;
    if (row0 >= n) return;
    int col0 = blockIdx.x * 64;

    extern __shared__ __align__(16) char dyn[];
    uint32_t smem = smem_u32(dyn);
    __shared__ int s_tok[256], s_orow[256];

    int tid = threadIdx.x;
    {
        int r = row0 + tid;
        int t, o;
        if (routed) { t = (r < n) ? g_tok[e][r] : g_tok[e][0];
                      o = (r < n) ? g_slot[e][r] : 0; }
        else        { t = (r < n) ? r : 0; o = t; }
        s_tok[tid] = t; s_orow[tid] = o;
    }
    __syncthreads();

    int w = tid >> 5, lane = tid & 31;
    int wm = (w >> 1) * 64, wn = (w & 1) * 32;
    int gi = lane >> 2, tig = lane & 3;

    float cg[4][4][4], cu[4][4][4];
#pragma unroll
    for (int mt = 0; mt < 4; mt++)
#pragma unroll
        for (int nt = 0; nt < 4; nt++)
#pragma unroll
            for (int i = 0; i < 4; i++) { cg[mt][nt][i] = 0.f; cu[mt][nt][i] = 0.f; }

    auto issue = [&](int c) {
        uint32_t base = smem + (c & 3) * STAGE1;
        uint32_t As = base, Bg_s = base + 32768, Bu_s = base + 40960;
        int k0 = c * 32;
#pragma unroll
        for (int it = 0; it < 8; it++) {
            int i = tid + it * 256; int r = i >> 3, q = i & 7;
            uint32_t d = As + r * 128 + ((q ^ (r & 7)) << 4);
            CP_ASYNC16(d, Xt + (size_t)s_tok[r] * HD + k0 + q * 4);
        }
#pragma unroll
        for (int it = 0; it < 2; it++) {
            int i = tid + it * 256; int nn = i >> 3, g = i & 7;
            uint32_t d = nn * 128 + ((g ^ (nn & 7)) << 4);
            CP_ASYNC16(Bg_s + d, Wg + (size_t)(col0 + nn) * HD + k0 + g * 4);
            CP_ASYNC16(Bu_s + d, Wu + (size_t)(col0 + nn) * HD + k0 + g * 4);
        }
    };
    auto compute = [&](uint32_t base) {
        uint32_t As = base, Bg_s = base + 32768, Bu_s = base + 40960;
        uint32_t bg[4][4], bu[4][4];
#pragma unroll
        for (int ks = 0; ks < 4; ks++) {
            if ((ks & 1) == 0) {
#pragma unroll
                for (int nt = 0; nt < 4; nt++) {
                    int row = wn + nt * 8 + (lane & 7);
                    int gr = ks * 2 + (lane >> 3);
                    uint32_t off = row * 128 + ((gr ^ (row & 7)) << 4);
                    LDSM_X4(bg[nt][0], bg[nt][1], bg[nt][2], bg[nt][3], Bg_s + off);
                    LDSM_X4(bu[nt][0], bu[nt][1], bu[nt][2], bu[nt][3], Bu_s + off);
                }
            }
            uint32_t a[4][4];
#pragma unroll
            for (int mt = 0; mt < 4; mt++) {
                int row = wm + mt * 16 + (lane & 7) + ((lane >> 3) & 1) * 8;
                int gr = ks * 2 + (lane >> 4);
                uint32_t off = row * 128 + ((gr ^ (row & 7)) << 4);
                LDSM_X4(a[mt][0], a[mt][1], a[mt][2], a[mt][3], As + off);
            }
            int o = (ks & 1) * 2;
#pragma unroll
            for (int mt = 0; mt < 4; mt++)
#pragma unroll
                for (int nt = 0; nt < 4; nt++) {
                    MMA8(cg[mt][nt], a[mt], bg[nt][o], bg[nt][o + 1]);
                    MMA8(cu[mt][nt], a[mt], bu[nt][o], bu[nt][o + 1]);
                }
        }
    };

    const int NCH = HD / 32;  // 32
    issue(0); CP_COMMIT();
    issue(1); CP_COMMIT();
    issue(2); CP_COMMIT();
    for (int c = 0; c < NCH; c++) {
        CP_WAIT2();
        __syncthreads();
        if (c + 3 < NCH) issue(c + 3);
        CP_COMMIT();
        compute(smem + (c & 3) * STAGE1);
    }

    // epilogue: silu(g)*u, tf32-rounded float2 stores to gathered rows
#pragma unroll
    for (int mt = 0; mt < 4; mt++)
#pragma unroll
        for (int nt = 0; nt < 4; nt++) {
            int col = col0 + wn + nt * 8 + tig * 2;
#pragma unroll
            for (int h = 0; h < 2; h++) {
                int lr = wm + mt * 16 + gi + h * 8;
                if (row0 + lr < n) {
                    float g0 = cg[mt][nt][h * 2], g1 = cg[mt][nt][h * 2 + 1];
                    float u0 = cu[mt][nt][h * 2], u1 = cu[mt][nt][h * 2 + 1];
                    float2 o;
                    o.x = __uint_as_float(to_tf32(g0 / (1.f + expf(-g0)) * u0));
                    o.y = __uint_as_float(to_tf32(g1 / (1.f + expf(-g1)) * u1));
                    *(float2*)(Act + (size_t)s_orow[lr] * ID + col) = o;
                }
            }
        }
}

// ---------------- GEMM 2: Out = Act @ Wd ----------------
// BM=256, BN=128, BK=32. 256 threads = 8 warps (4M x 2N); warp tile 64x64.
__global__ __launch_bounds__(256, 1)
void gemm2_mma(const float* __restrict__ ActR,
               const float* __restrict__ ActS,
               const float* __restrict__ Wdt_base,
               const float* __restrict__ Sdt,
               float* __restrict__ OutR,
               float* __restrict__ OutS) {
    int e = blockIdx.z;
    int n; const float *Wd, *Src; float* Out; int routed = (e < ED);
    if (routed) { n = g_cnt[e]; Wd = Wdt_base + (size_t)e * ID * HD; Src = ActR; Out = OutR; }
    else        { n = TT;       Wd = Sdt;                             Src = ActS; Out = OutS; }
    int row0 = blockIdx.y * 256;
    if (row0 >= n) return;
    int col0 = blockIdx.x * 128;

    extern __shared__ __align__(16) char dyn[];
    uint32_t smem = smem_u32(dyn);
    __shared__ int s_row[256];

    int tid = threadIdx.x;
    {
        int r = row0 + tid;
        int a;
        if (routed) a = (r < n) ? g_slot[e][r] : 0;
        else        a = (r < n) ? r : 0;
        s_row[tid] = a;
    }
    __syncthreads();

    int w = tid >> 5, lane = tid & 31;
    int wm = (w >> 1) * 64, wn = (w & 1) * 64;
    int gi = lane >> 2, tig = lane & 3;

    float cc[4][8][4];
#pragma unroll
    for (int mt = 0; mt < 4; mt++)
#pragma unroll
        for (int nt = 0; nt < 8; nt++)
#pragma unroll
            for (int i = 0; i < 4; i++) cc[mt][nt][i] = 0.f;

    auto issue = [&](int c) {
        uint32_t base = smem + (c & 3) * STAGE2;
        uint32_t As = base, Bs = base + 32768;
        int k0 = c * 32;
#pragma unroll
        for (int it = 0; it < 8; it++) {
            int i = tid + it * 256; int r = i >> 3, q = i & 7;
            uint32_t d = As + r * 128 + ((q ^ (r & 7)) << 4);
            CP_ASYNC16(d, Src + (size_t)s_row[r] * ID + k0 + q * 4);
        }
#pragma unroll
        for (int it = 0; it < 4; it++) {
            int i = tid + it * 256; int nn = i >> 3, g = i & 7;
            uint32_t d = Bs + nn * 128 + ((g ^ (nn & 7)) << 4);
            CP_ASYNC16(d, Wd + (size_t)(col0 + nn) * ID + k0 + g * 4);
        }
    };
    auto compute = [&](uint32_t base) {
        uint32_t As = base, Bs = base + 32768;
        uint32_t b[8][4];
#pragma unroll
        for (int ks = 0; ks < 4; ks++) {
            if ((ks & 1) == 0) {
#pragma unroll
                for (int nt = 0; nt < 8; nt++) {
                    int row = wn + nt * 8 + (lane & 7);
                    int gr = ks * 2 + (lane >> 3);
                    uint32_t off = row * 128 + ((gr ^ (row & 7)) << 4);
                    LDSM_X4(b[nt][0], b[nt][1], b[nt][2], b[nt][3], Bs + off);
                }
            }
            uint32_t a[4][4];
#pragma unroll
            for (int mt = 0; mt < 4; mt++) {
                int row = wm + mt * 16 + (lane & 7) + ((lane >> 3) & 1) * 8;
                int gr = ks * 2 + (lane >> 4);
                uint32_t off = row * 128 + ((gr ^ (row & 7)) << 4);
                LDSM_X4(a[mt][0], a[mt][1], a[mt][2], a[mt][3], As + off);
            }
            int o = (ks & 1) * 2;
#pragma unroll
            for (int mt = 0; mt < 4; mt++)
#pragma unroll
                for (int nt = 0; nt < 8; nt++)
                    MMA8(cc[mt][nt], a[mt], b[nt][o], b[nt][o + 1]);
        }
    };

    const int NCH = ID / 32;  // 86
    issue(0); CP_COMMIT();
    issue(1); CP_COMMIT();
    issue(2); CP_COMMIT();
    for (int c = 0; c < NCH; c++) {
        CP_WAIT2();
        __syncthreads();
        if (c + 3 < NCH) issue(c + 3);
        CP_COMMIT();
        compute(smem + (c & 3) * STAGE2);
    }

#pragma unroll
    for (int mt = 0; mt < 4; mt++)
#pragma unroll
        for (int nt = 0; nt < 8; nt++) {
            int col = col0 + wn + nt * 8 + tig * 2;
#pragma unroll
            for (int h = 0; h < 2; h++) {
                int lr = wm + mt * 16 + gi + h * 8;
                if (row0 + lr < n) {
                    float2 o;
                    o.x = cc[mt][nt][h * 2];
                    o.y = cc[mt][nt][h * 2 + 1];
                    *(float2*)(Out + (size_t)s_row[lr] * HD + col) = o;
                }
            }
        }
}

// out[t] += w0*outk[2t] + w1*outk[2t+1]
__global__ void combine_kernel(float* __restrict__ out) {
    int t = blockIdx.x;
    int h = threadIdx.x;
    float w0 = g_wslot[2 * t];
    float w1 = g_wslot[2 * t + 1];
    size_t base = (size_t)(2 * t) * HD + h;
    float v = out[(size_t)t * HD + h];
    v += w0 * g_outk[base] + w1 * g_outk[base + HD];
    out[(size_t)t * HD + h] = v;
}

// ---------------- launch ----------------
extern "C" void kernel_launch(void* const* d_in, const int* in_sizes, int n_in,
                              void* d_out, int out_size) {
    const float* x  = (const float*)d_in[0];
    const float* gw = (const float*)d_in[1];
    const float* wg = (const float*)d_in[2];
    const float* wu = (const float*)d_in[3];
    const float* wd = (const float*)d_in[4];
    const float* sg = (const float*)d_in[5];
    const float* su = (const float*)d_in[6];
    const float* sd = (const float*)d_in[7];
    float* out = (float*)d_out;

    const int SMEM_BYTES = 4 * STAGE1;  // 192KB
    cudaFuncSetAttribute(gemm1_mma, cudaFuncAttributeMaxDynamicSharedMemorySize, SMEM_BYTES);
    cudaFuncSetAttribute(gemm2_mma, cudaFuncAttributeMaxDynamicSharedMemorySize, SMEM_BYTES);

    float* xt;   cudaGetSymbolAddress((void**)&xt,   g_xt);
    float* wgt;  cudaGetSymbolAddress((void**)&wgt,  g_wgt);
    float* wut;  cudaGetSymbolAddress((void**)&wut,  g_wut);
    float* wdt;  cudaGetSymbolAddress((void**)&wdt,  g_wdt);
    float* sgt;  cudaGetSymbolAddress((void**)&sgt,  g_sgt);
    float* sut;  cudaGetSymbolAddress((void**)&sut,  g_sut);
    float* sdt;  cudaGetSymbolAddress((void**)&sdt,  g_sdt);
    float* act;  cudaGetSymbolAddress((void**)&act,  g_act);
    float* outk; cudaGetSymbolAddress((void**)&outk, g_outk);
    float* sact; cudaGetSymbolAddress((void**)&sact, g_sact);

    zero_cnt_kernel<<<1, 32>>>();
    gate_kernel<<<TT / 8, 256>>>(x, gw);

    // pre-pass: tf32 rounding + weight transposes
    convx_kernel<<<TT * HD / 1024, 256>>>(x);
    {
        dim3 gtu(ID / 32, HD / 32, ED);   // [H][I] -> [I][H]
        transpose_cvt<<<gtu, 256>>>(wg, wgt, HD, ID);
        transpose_cvt<<<gtu, 256>>>(wu, wut, HD, ID);
        dim3 gtd(HD / 32, ID / 32, ED);   // [I][H] -> [H][I]
        transpose_cvt<<<gtd, 256>>>(wd, wdt, ID, HD);
        dim3 gsu(ID / 32, HD / 32, 1);
        transpose_cvt<<<gsu, 256>>>(sg, sgt, HD, ID);
        transpose_cvt<<<gsu, 256>>>(su, sut, HD, ID);
        dim3 gsd(HD / 32, ID / 32, 1);
        transpose_cvt<<<gsd, 256>>>(sd, sdt, ID, HD);
    }

    // fused routed (z=0..7) + shared (z=8) launches
    {
        dim3 g1(ID / 64, TT / 256, ED + 1);     // (43, 32, 9)
        gemm1_mma<<<g1, 256, SMEM_BYTES>>>(xt, wgt, wut, sgt, sut, act, sact);
        dim3 g2(HD / 128, TT / 256, ED + 1);    // (8, 32, 9)
        gemm2_mma<<<g2, 256, SMEM_BYTES>>>(act, sact, wdt, sdt, outk, out);
    }
    combine_kernel<<<TT, HD>>>(out);
}

// round 6
// speedup vs baseline: 5.7381x; 1.5814x over previous
#include <cuda_runtime.h>
#include <cuda_fp16.h>
#include <math.h>
#include <stdint.h>

#define TT 8192      // tokens = B*S
#define HD 1024      // hidden
#define ID 2752      // intermediate
#define ED 8         // experts
#define KD 2         // top-k

// ---------------- device scratch ----------------
__device__ int    g_cnt[ED];
__device__ int    g_tok[ED][TT];
__device__ int    g_slot[ED][TT];
__device__ float  g_wslot[TT * KD];
__device__ __half g_act[(size_t)TT * KD * ID];   // routed activations fp16 (slot-major)
__device__ __half g_sact[(size_t)TT * ID];       // shared-expert activations fp16
__device__ float  g_outk[(size_t)TT * KD * HD];  // routed outputs (slot-major)
// fp16 converted / transposed operands
__device__ __half g_xh[(size_t)TT * HD];         // x fp16
__device__ __half g_wgt[(size_t)ED * HD * ID];   // Wg^T  [E][I][H]
__device__ __half g_wut[(size_t)ED * HD * ID];   // Wu^T  [E][I][H]
__device__ __half g_wdt[(size_t)ED * ID * HD];   // Wd^T  [E][H][I]
__device__ __half g_sgt[(size_t)HD * ID];        // sg^T  [I][H]
__device__ __half g_sut[(size_t)HD * ID];        // su^T  [I][H]
__device__ __half g_sdt[(size_t)ID * HD];        // sd^T  [H][I]

// ---------------- helpers ----------------
__device__ __forceinline__ uint32_t smem_u32(const void* p) {
    uint32_t a;
    asm("{ .reg .u64 t; cvta.to.shared.u64 t, %1; cvt.u32.u64 %0, t; }" : "=r"(a) : "l"(p));
    return a;
}

#define LDSM_X4(r0, r1, r2, r3, addr) \
    asm volatile("ldmatrix.sync.aligned.m8n8.x4.shared.b16 {%0,%1,%2,%3}, [%4];" \
                 : "=r"(r0), "=r"(r1), "=r"(r2), "=r"(r3) : "r"(addr))

#define MMA16(c, a, b0, b1) \
    asm volatile("mma.sync.aligned.m16n8k16.row.col.f32.f16.f16.f32 " \
                 "{%0,%1,%2,%3}, {%4,%5,%6,%7}, {%8,%9}, {%0,%1,%2,%3};" \
                 : "+f"((c)[0]), "+f"((c)[1]), "+f"((c)[2]), "+f"((c)[3]) \
                 : "r"((a)[0]), "r"((a)[1]), "r"((a)[2]), "r"((a)[3]), "r"(b0), "r"(b1))

#define CP_ASYNC16(dst, src) \
    asm volatile("cp.async.cg.shared.global [%0], [%1], 16;" :: "r"(dst), "l"(src) : "memory")
#define CP_COMMIT() asm volatile("cp.async.commit_group;" ::: "memory")
#define CP_WAIT2()  asm volatile("cp.async.wait_group 2;" ::: "memory")

// 64B-row XOR swizzle: r = row, c = 16B chunk (0..3)
__device__ __forceinline__ uint32_t swz(int r, int c) {
    return (uint32_t)(r * 64 + ((c ^ ((r >> 1) & 3)) << 4));
}

#define STAGE 24576   // A 16KB + B(8KB total)
#define NSTAGE 4

// ---------------- small kernels ----------------
__global__ void zero_cnt_kernel() {
    if (threadIdx.x < ED) g_cnt[threadIdx.x] = 0;
}

__global__ void gate_kernel(const float* __restrict__ x,
                            const float* __restrict__ gw) {
    int warp = (blockIdx.x * blockDim.x + threadIdx.x) >> 5;
    int lane = threadIdx.x & 31;
    if (warp >= TT) return;
    const float* xr = x + (size_t)warp * HD;

    float acc[ED];
#pragma unroll
    for (int e = 0; e < ED; e++) acc[e] = 0.f;
    for (int h = lane; h < HD; h += 32) {
        float xv = xr[h];
#pragma unroll
        for (int e = 0; e < ED; e++) acc[e] += xv * gw[e * HD + h];
    }
#pragma unroll
    for (int off = 16; off > 0; off >>= 1) {
#pragma unroll
        for (int e = 0; e < ED; e++)
            acc[e] += __shfl_xor_sync(0xFFFFFFFFu, acc[e], off);
    }
    if (lane == 0) {
        float m = acc[0];
#pragma unroll
        for (int e = 1; e < ED; e++) m = fmaxf(m, acc[e]);
        float ex[ED], s = 0.f;
#pragma unroll
        for (int e = 0; e < ED; e++) { ex[e] = expf(acc[e] - m); s += ex[e]; }
        int i0 = 0;
#pragma unroll
        for (int e = 1; e < ED; e++) if (ex[e] > ex[i0]) i0 = e;
        int i1 = -1;
#pragma unroll
        for (int e = 0; e < ED; e++) {
            if (e == i0) continue;
            if (i1 < 0 || ex[e] > ex[i1]) i1 = e;
        }
        float p0 = ex[i0] / s, p1 = ex[i1] / s;
        float d  = p0 + p1 + 1e-20f;
        int t = warp;
        int pos0 = atomicAdd(&g_cnt[i0], 1);
        g_tok[i0][pos0]  = t;
        g_slot[i0][pos0] = 2 * t;
        int pos1 = atomicAdd(&g_cnt[i1], 1);
        g_tok[i1][pos1]  = t;
        g_slot[i1][pos1] = 2 * t + 1;
        g_wslot[2 * t]     = p0 / d;
        g_wslot[2 * t + 1] = p1 / d;
    }
}

// x -> fp16 copy
__global__ void convx_kernel(const float* __restrict__ x) {
    size_t i = ((size_t)blockIdx.x * 256 + threadIdx.x) * 4;
    float4 v = *(const float4*)(x + i);
    __half2 h0 = __floats2half2_rn(v.x, v.y);
    __half2 h1 = __floats2half2_rn(v.z, v.w);
    *(__half2*)(g_xh + i)     = h0;
    *(__half2*)(g_xh + i + 2) = h1;
}

// src f32 [E][K][N] row-major -> dst fp16 [E][N][K]
__global__ void transpose_cvt(const float* __restrict__ src, __half* __restrict__ dst,
                              int K, int N) {
    __shared__ float tile[32][33];
    src += (size_t)blockIdx.z * K * N;
    dst += (size_t)blockIdx.z * K * N;
    int n0 = blockIdx.x * 32, k0 = blockIdx.y * 32;
    int tx = threadIdx.x & 31, ty = threadIdx.x >> 5;  // 256 thr
#pragma unroll
    for (int i = 0; i < 32; i += 8)
        tile[ty + i][tx] = src[(size_t)(k0 + ty + i) * N + n0 + tx];
    __syncthreads();
#pragma unroll
    for (int i = 0; i < 32; i += 8)
        dst[(size_t)(n0 + ty + i) * K + k0 + tx] = __float2half_rn(tile[tx][ty + i]);
}

// ---------------- GEMM 1: act = silu(X@Wg) * (X@Wu)  [fp16 MMA] ----------------
// BM=256, BN=64, BK=32. 8 warps (4M x 2N); warp tile 64x32 per matrix.
// z<8: routed expert z; z==8: shared expert.
__global__ __launch_bounds__(256, 1)
void gemm1_mma(const __half* __restrict__ Xh,
               const __half* __restrict__ Wgt_base,
               const __half* __restrict__ Wut_base,
               const __half* __restrict__ Sgt,
               const __half* __restrict__ Sut,
               __half* __restrict__ ActR,
               __half* __restrict__ ActS) {
    int e = blockIdx.z;
    int n; const __half *Wg, *Wu; __half* Act; int routed = (e < ED);
    if (routed) { n = g_cnt[e]; Wg = Wgt_base + (size_t)e * HD * ID; Wu = Wut_base + (size_t)e * HD * ID; Act = ActR; }
    else        { n = TT;       Wg = Sgt;                             Wu = Sut;                             Act = ActS; }
    int row0 = blockIdx.y * 256;
    if (row0 >= n) return;
    int col0 = blockIdx.x * 64;

    extern __shared__ __align__(16) char dyn[];
    uint32_t smem = smem_u32(dyn);
    __shared__ int s_tok[256], s_orow[256];

    int tid = threadIdx.x;
    {
        int r = row0 + tid;
        int t, o;
        if (routed) { t = (r < n) ? g_tok[e][r] : g_tok[e][0];
                      o = (r < n) ? g_slot[e][r] : 0; }
        else        { t = (r < n) ? r : 0; o = t; }
        s_tok[tid] = t; s_orow[tid] = o;
    }
    __syncthreads();

    int w = tid >> 5, lane = tid & 31;
    int wm = (w >> 1) * 64, wn = (w & 1) * 32;
    int gi = lane >> 2, tig = lane & 3;
    int l15 = lane & 15, l16 = lane >> 4;

    float cg[4][4][4], cu[4][4][4];
#pragma unroll
    for (int mt = 0; mt < 4; mt++)
#pragma unroll
        for (int nt = 0; nt < 4; nt++)
#pragma unroll
            for (int i = 0; i < 4; i++) { cg[mt][nt][i] = 0.f; cu[mt][nt][i] = 0.f; }

    auto issue = [&](int c) {
        uint32_t base = smem + (c & (NSTAGE - 1)) * STAGE;
        uint32_t As = base, Bg_s = base + 16384, Bu_s = base + 20480;
        int k0 = c * 32;
        // A: 256 rows x 32 fp16 (64B rows)
#pragma unroll
        for (int it = 0; it < 4; it++) {
            int i = tid + it * 256; int r = i >> 2, q = i & 3;
            CP_ASYNC16(As + swz(r, q), Xh + (size_t)s_tok[r] * HD + k0 + q * 8);
        }
        // Bg/Bu: 64 rows x 32 fp16
        {
            int r = tid >> 2, q = tid & 3;
            uint32_t d = swz(r, q);
            CP_ASYNC16(Bg_s + d, Wg + (size_t)(col0 + r) * HD + k0 + q * 8);
            CP_ASYNC16(Bu_s + d, Wu + (size_t)(col0 + r) * HD + k0 + q * 8);
        }
    };
    auto compute = [&](uint32_t base) {
        uint32_t As = base, Bg_s = base + 16384, Bu_s = base + 20480;
#pragma unroll
        for (int s = 0; s < 2; s++) {
            int c = s * 2 + l16;
            uint32_t a[4][4], bg[2][4], bu[2][4];
#pragma unroll
            for (int mt = 0; mt < 4; mt++) {
                int row = wm + mt * 16 + l15;
                LDSM_X4(a[mt][0], a[mt][1], a[mt][2], a[mt][3], As + swz(row, c));
            }
#pragma unroll
            for (int p = 0; p < 2; p++) {
                int row = wn + p * 16 + l15;
                uint32_t off = swz(row, c);
                LDSM_X4(bg[p][0], bg[p][1], bg[p][2], bg[p][3], Bg_s + off);
                LDSM_X4(bu[p][0], bu[p][1], bu[p][2], bu[p][3], Bu_s + off);
            }
#pragma unroll
            for (int mt = 0; mt < 4; mt++)
#pragma unroll
                for (int p = 0; p < 2; p++) {
                    MMA16(cg[mt][2 * p],     a[mt], bg[p][0], bg[p][2]);
                    MMA16(cg[mt][2 * p + 1], a[mt], bg[p][1], bg[p][3]);
                    MMA16(cu[mt][2 * p],     a[mt], bu[p][0], bu[p][2]);
                    MMA16(cu[mt][2 * p + 1], a[mt], bu[p][1], bu[p][3]);
                }
        }
    };

    const int NCH = HD / 32;  // 32
    issue(0); CP_COMMIT();
    issue(1); CP_COMMIT();
    issue(2); CP_COMMIT();
    for (int c = 0; c < NCH; c++) {
        CP_WAIT2();
        __syncthreads();
        if (c + 3 < NCH) issue(c + 3);
        CP_COMMIT();
        compute(smem + (c & (NSTAGE - 1)) * STAGE);
    }

    // epilogue: silu(g)*u, fp16 stores to gathered rows
#pragma unroll
    for (int mt = 0; mt < 4; mt++)
#pragma unroll
        for (int nt = 0; nt < 4; nt++) {
            int col = col0 + wn + nt * 8 + tig * 2;
#pragma unroll
            for (int h = 0; h < 2; h++) {
                int lr = wm + mt * 16 + gi + h * 8;
                if (row0 + lr < n) {
                    float g0 = cg[mt][nt][h * 2], g1 = cg[mt][nt][h * 2 + 1];
                    float u0 = cu[mt][nt][h * 2], u1 = cu[mt][nt][h * 2 + 1];
                    float o0 = g0 / (1.f + expf(-g0)) * u0;
                    float o1 = g1 / (1.f + expf(-g1)) * u1;
                    *(__half2*)(Act + (size_t)s_orow[lr] * ID + col) =
                        __floats2half2_rn(o0, o1);
                }
            }
        }
}

// ---------------- GEMM 2: Out = Act @ Wd  [fp16 MMA] ----------------
// BM=256, BN=128, BK=32. 8 warps (4M x 2N); warp tile 64x64.
__global__ __launch_bounds__(256, 1)
void gemm2_mma(const __half* __restrict__ ActR,
               const __half* __restrict__ ActS,
               const __half* __restrict__ Wdt_base,
               const __half* __restrict__ Sdt,
               float* __restrict__ OutR,
               float* __restrict__ OutS) {
    int e = blockIdx.z;
    int n; const __half *Wd, *Src; float* Out; int routed = (e < ED);
    if (routed) { n = g_cnt[e]; Wd = Wdt_base + (size_t)e * ID * HD; Src = ActR; Out = OutR; }
    else        { n = TT;       Wd = Sdt;                             Src = ActS; Out = OutS; }
    int row0 = blockIdx.y * 256;
    if (row0 >= n) return;
    int col0 = blockIdx.x * 128;

    extern __shared__ __align__(16) char dyn[];
    uint32_t smem = smem_u32(dyn);
    __shared__ int s_row[256];

    int tid = threadIdx.x;
    {
        int r = row0 + tid;
        int a;
        if (routed) a = (r < n) ? g_slot[e][r] : 0;
        else        a = (r < n) ? r : 0;
        s_row[tid] = a;
    }
    __syncthreads();

    int w = tid >> 5, lane = tid & 31;
    int wm = (w >> 1) * 64, wn = (w & 1) * 64;
    int gi = lane >> 2, tig = lane & 3;
    int l15 = lane & 15, l16 = lane >> 4;

    float cc[4][8][4];
#pragma unroll
    for (int mt = 0; mt < 4; mt++)
#pragma unroll
        for (int nt = 0; nt < 8; nt++)
#pragma unroll
            for (int i = 0; i < 4; i++) cc[mt][nt][i] = 0.f;

    auto issue = [&](int c) {
        uint32_t base = smem + (c & (NSTAGE - 1)) * STAGE;
        uint32_t As = base, Bs = base + 16384;
        int k0 = c * 32;
#pragma unroll
        for (int it = 0; it < 4; it++) {
            int i = tid + it * 256; int r = i >> 2, q = i & 3;
            CP_ASYNC16(As + swz(r, q), Src + (size_t)s_row[r] * ID + k0 + q * 8);
        }
#pragma unroll
        for (int it = 0; it < 2; it++) {
            int i = tid + it * 256; int r = i >> 2, q = i & 3;
            CP_ASYNC16(Bs + swz(r, q), Wd + (size_t)(col0 + r) * ID + k0 + q * 8);
        }
    };
    auto compute = [&](uint32_t base) {
        uint32_t As = base, Bs = base + 16384;
#pragma unroll
        for (int s = 0; s < 2; s++) {
            int c = s * 2 + l16;
            uint32_t a[4][4], b[4][4];
#pragma unroll
            for (int mt = 0; mt < 4; mt++) {
                int row = wm + mt * 16 + l15;
                LDSM_X4(a[mt][0], a[mt][1], a[mt][2], a[mt][3], As + swz(row, c));
            }
#pragma unroll
            for (int p = 0; p < 4; p++) {
                int row = wn + p * 16 + l15;
                LDSM_X4(b[p][0], b[p][1], b[p][2], b[p][3], Bs + swz(row, c));
            }
#pragma unroll
            for (int mt = 0; mt < 4; mt++)
#pragma unroll
                for (int p = 0; p < 4; p++) {
                    MMA16(cc[mt][2 * p],     a[mt], b[p][0], b[p][2]);
                    MMA16(cc[mt][2 * p + 1], a[mt], b[p][1], b[p][3]);
                }
        }
    };

    const int NCH = ID / 32;  // 86
    issue(0); CP_COMMIT();
    issue(1); CP_COMMIT();
    issue(2); CP_COMMIT();
    for (int c = 0; c < NCH; c++) {
        CP_WAIT2();
        __syncthreads();
        if (c + 3 < NCH) issue(c + 3);
        CP_COMMIT();
        compute(smem + (c & (NSTAGE - 1)) * STAGE);
    }

#pragma unroll
    for (int mt = 0; mt < 4; mt++)
#pragma unroll
        for (int nt = 0; nt < 8; nt++) {
            int col = col0 + wn + nt * 8 + tig * 2;
#pragma unroll
            for (int h = 0; h < 2; h++) {
                int lr = wm + mt * 16 + gi + h * 8;
                if (row0 + lr < n) {
                    float2 o;
                    o.x = cc[mt][nt][h * 2];
                    o.y = cc[mt][nt][h * 2 + 1];
                    *(float2*)(Out + (size_t)s_row[lr] * HD + col) = o;
                }
            }
        }
}

// out[t] += w0*outk[2t] + w1*outk[2t+1]
__global__ void combine_kernel(float* __restrict__ out) {
    int t = blockIdx.x;
    int h = threadIdx.x;
    float w0 = g_wslot[2 * t];
    float w1 = g_wslot[2 * t + 1];
    size_t base = (size_t)(2 * t) * HD + h;
    float v = out[(size_t)t * HD + h];
    v += w0 * g_outk[base] + w1 * g_outk[base + HD];
    out[(size_t)t * HD + h] = v;
}

// ---------------- launch ----------------
extern "C" void kernel_launch(void* const* d_in, const int* in_sizes, int n_in,
                              void* d_out, int out_size) {
    const float* x  = (const float*)d_in[0];
    const float* gw = (const float*)d_in[1];
    const float* wg = (const float*)d_in[2];
    const float* wu = (const float*)d_in[3];
    const float* wd = (const float*)d_in[4];
    const float* sg = (const float*)d_in[5];
    const float* su = (const float*)d_in[6];
    const float* sd = (const float*)d_in[7];
    float* out = (float*)d_out;

    const int SMEM_BYTES = NSTAGE * STAGE;  // 96KB
    cudaFuncSetAttribute(gemm1_mma, cudaFuncAttributeMaxDynamicSharedMemorySize, SMEM_BYTES);
    cudaFuncSetAttribute(gemm2_mma, cudaFuncAttributeMaxDynamicSharedMemorySize, SMEM_BYTES);

    __half* xh;  cudaGetSymbolAddress((void**)&xh,  g_xh);
    __half* wgt; cudaGetSymbolAddress((void**)&wgt, g_wgt);
    __half* wut; cudaGetSymbolAddress((void**)&wut, g_wut);
    __half* wdt; cudaGetSymbolAddress((void**)&wdt, g_wdt);
    __half* sgt; cudaGetSymbolAddress((void**)&sgt, g_sgt);
    __half* sut; cudaGetSymbolAddress((void**)&sut, g_sut);
    __half* sdt; cudaGetSymbolAddress((void**)&sdt, g_sdt);
    __half* act; cudaGetSymbolAddress((void**)&act, g_act);
    __half* sact;cudaGetSymbolAddress((void**)&sact,g_sact);
    float* outk; cudaGetSymbolAddress((void**)&outk,g_outk);

    zero_cnt_kernel<<<1, 32>>>();
    gate_kernel<<<TT / 8, 256>>>(x, gw);

    // pre-pass: fp16 conversion + weight transposes
    convx_kernel<<<TT * HD / 1024, 256>>>(x);
    {
        dim3 gtu(ID / 32, HD / 32, ED);   // [H][I] -> [I][H]
        transpose_cvt<<<gtu, 256>>>(wg, wgt, HD, ID);
        transpose_cvt<<<gtu, 256>>>(wu, wut, HD, ID);
        dim3 gtd(HD / 32, ID / 32, ED);   // [I][H] -> [H][I]
        transpose_cvt<<<gtd, 256>>>(wd, wdt, ID, HD);
        dim3 gsu(ID / 32, HD / 32, 1);
        transpose_cvt<<<gsu, 256>>>(sg, sgt, HD, ID);
        transpose_cvt<<<gsu, 256>>>(su, sut, HD, ID);
        dim3 gsd(HD / 32, ID / 32, 1);
        transpose_cvt<<<gsd, 256>>>(sd, sdt, ID, HD);
    }

    // fused routed (z=0..7) + shared (z=8) launches
    {
        dim3 g1(ID / 64, TT / 256, ED + 1);     // (43, 32, 9)
        gemm1_mma<<<g1, 256, SMEM_BYTES>>>(xh, wgt, wut, sgt, sut, act, sact);
        dim3 g2(HD / 128, TT / 256, ED + 1);    // (8, 32, 9)
        gemm2_mma<<<g2, 256, SMEM_BYTES>>>(act, sact, wdt, sdt, outk, out);
    }
    combine_kernel<<<TT, HD>>>(out);
}

// round 7
// speedup vs baseline: 6.5863x; 1.1478x over previous
#include <cuda_runtime.h>
#include <cuda_fp16.h>
#include <math.h>
#include <stdint.h>

#define TT 8192      // tokens = B*S
#define HD 1024      // hidden
#define ID 2752      // intermediate
#define ED 8         // experts
#define KD 2         // top-k

// ---------------- device scratch ----------------
__device__ int    g_cnt[ED];
__device__ int    g_tok[ED][TT];
__device__ int    g_slot[ED][TT];
__device__ float  g_wslot[TT * KD];
__device__ __half g_act[(size_t)TT * KD * ID];   // routed activations fp16 (slot-major)
__device__ __half g_sact[(size_t)TT * ID];       // shared-expert activations fp16
__device__ float  g_outk[(size_t)TT * KD * HD];  // routed outputs (slot-major)
// fp16 converted / transposed operands
__device__ __half g_xh[(size_t)TT * HD];         // x fp16
__device__ __half g_wgt[(size_t)ED * HD * ID];   // Wg^T  [E][I][H]
__device__ __half g_wut[(size_t)ED * HD * ID];   // Wu^T  [E][I][H]
__device__ __half g_wdt[(size_t)ED * ID * HD];   // Wd^T  [E][H][I]
__device__ __half g_sgt[(size_t)HD * ID];        // sg^T  [I][H]
__device__ __half g_sut[(size_t)HD * ID];        // su^T  [I][H]
__device__ __half g_sdt[(size_t)ID * HD];        // sd^T  [H][I]

// ---------------- helpers ----------------
__device__ __forceinline__ uint32_t smem_u32(const void* p) {
    uint32_t a;
    asm("{ .reg .u64 t; cvta.to.shared.u64 t, %1; cvt.u32.u64 %0, t; }" : "=r"(a) : "l"(p));
    return a;
}

#define LDSM_X4(r0, r1, r2, r3, addr) \
    asm volatile("ldmatrix.sync.aligned.m8n8.x4.shared.b16 {%0,%1,%2,%3}, [%4];" \
                 : "=r"(r0), "=r"(r1), "=r"(r2), "=r"(r3) : "r"(addr))

#define MMA16(c, a, b0, b1) \
    asm volatile("mma.sync.aligned.m16n8k16.row.col.f32.f16.f16.f32 " \
                 "{%0,%1,%2,%3}, {%4,%5,%6,%7}, {%8,%9}, {%0,%1,%2,%3};" \
                 : "+f"((c)[0]), "+f"((c)[1]), "+f"((c)[2]), "+f"((c)[3]) \
                 : "r"((a)[0]), "r"((a)[1]), "r"((a)[2]), "r"((a)[3]), "r"(b0), "r"(b1))

#define CP_ASYNC16(dst, src) \
    asm volatile("cp.async.cg.shared.global [%0], [%1], 16;" :: "r"(dst), "l"(src) : "memory")
#define CP_COMMIT() asm volatile("cp.async.commit_group;" ::: "memory")
#define CP_WAIT2()  asm volatile("cp.async.wait_group 2;" ::: "memory")

// 64B-row XOR swizzle: r = row, c = 16B chunk (0..3)
__device__ __forceinline__ uint32_t swz(int r, int c) {
    return (uint32_t)(r * 64 + ((c ^ ((r >> 1) & 3)) << 4));
}

#define STAGE1 16384   // gemm1: A 8KB + Bg 4KB + Bu 4KB
#define STAGE2 24576   // gemm2: A 16KB + B 8KB
#define NSTAGE 4

// ---------------- small kernels ----------------
__global__ void zero_cnt_kernel() {
    if (threadIdx.x < ED) g_cnt[threadIdx.x] = 0;
}

__global__ void gate_kernel(const float* __restrict__ x,
                            const float* __restrict__ gw) {
    int warp = (blockIdx.x * blockDim.x + threadIdx.x) >> 5;
    int lane = threadIdx.x & 31;
    if (warp >= TT) return;
    const float* xr = x + (size_t)warp * HD;

    float acc[ED];
#pragma unroll
    for (int e = 0; e < ED; e++) acc[e] = 0.f;
    for (int h = lane; h < HD; h += 32) {
        float xv = xr[h];
#pragma unroll
        for (int e = 0; e < ED; e++) acc[e] += xv * gw[e * HD + h];
    }
#pragma unroll
    for (int off = 16; off > 0; off >>= 1) {
#pragma unroll
        for (int e = 0; e < ED; e++)
            acc[e] += __shfl_xor_sync(0xFFFFFFFFu, acc[e], off);
    }
    if (lane == 0) {
        float m = acc[0];
#pragma unroll
        for (int e = 1; e < ED; e++) m = fmaxf(m, acc[e]);
        float ex[ED], s = 0.f;
#pragma unroll
        for (int e = 0; e < ED; e++) { ex[e] = expf(acc[e] - m); s += ex[e]; }
        int i0 = 0;
#pragma unroll
        for (int e = 1; e < ED; e++) if (ex[e] > ex[i0]) i0 = e;
        int i1 = -1;
#pragma unroll
        for (int e = 0; e < ED; e++) {
            if (e == i0) continue;
            if (i1 < 0 || ex[e] > ex[i1]) i1 = e;
        }
        float p0 = ex[i0] / s, p1 = ex[i1] / s;
        float d  = p0 + p1 + 1e-20f;
        int t = warp;
        int pos0 = atomicAdd(&g_cnt[i0], 1);
        g_tok[i0][pos0]  = t;
        g_slot[i0][pos0] = 2 * t;
        int pos1 = atomicAdd(&g_cnt[i1], 1);
        g_tok[i1][pos1]  = t;
        g_slot[i1][pos1] = 2 * t + 1;
        g_wslot[2 * t]     = p0 / d;
        g_wslot[2 * t + 1] = p1 / d;
    }
}

// x -> fp16 copy
__global__ void convx_kernel(const float* __restrict__ x) {
    size_t i = ((size_t)blockIdx.x * 256 + threadIdx.x) * 4;
    float4 v = *(const float4*)(x + i);
    *(__half2*)(g_xh + i)     = __floats2half2_rn(v.x, v.y);
    *(__half2*)(g_xh + i + 2) = __floats2half2_rn(v.z, v.w);
}

// transpose+cvt body: src f32 [K][N] -> dst fp16 [N][K], one 32x32 tile per block
__device__ __forceinline__ void tr_tile(const float* __restrict__ src,
                                        __half* __restrict__ dst,
                                        int K, int N, int k0, int n0) {
    __shared__ float tile[32][33];
    int tx = threadIdx.x & 31, ty = threadIdx.x >> 5;  // 256 thr
#pragma unroll
    for (int i = 0; i < 32; i += 8)
        tile[ty + i][tx] = src[(size_t)(k0 + ty + i) * N + n0 + tx];
    __syncthreads();
#pragma unroll
    for (int i = 0; i < 32; i += 8)
        dst[(size_t)(n0 + ty + i) * K + k0 + tx] = __float2half_rn(tile[tx][ty + i]);
}

// merged routed-weight transposes: z<8 wg, z<16 wu, z<24 wd. 2752 tiles each.
__global__ void transpose_big(const float* __restrict__ wg, const float* __restrict__ wu,
                              const float* __restrict__ wd,
                              __half* __restrict__ wgt, __half* __restrict__ wut,
                              __half* __restrict__ wdt) {
    int z = blockIdx.z;
    const float* src; __half* dst; int K, N;
    if (z < 8)       { src = wg + (size_t)z * HD * ID;        dst = wgt + (size_t)z * HD * ID;        K = HD; N = ID; }
    else if (z < 16) { src = wu + (size_t)(z - 8) * HD * ID;  dst = wut + (size_t)(z - 8) * HD * ID;  K = HD; N = ID; }
    else             { src = wd + (size_t)(z - 16) * ID * HD; dst = wdt + (size_t)(z - 16) * ID * HD; K = ID; N = HD; }
    int tn = N / 32;
    int n0 = (blockIdx.x % tn) * 32, k0 = (blockIdx.x / tn) * 32;
    tr_tile(src, dst, K, N, k0, n0);
}

// merged shared-weight transposes: z=0 sg, z=1 su, z=2 sd
__global__ void transpose_small(const float* __restrict__ sg, const float* __restrict__ su,
                                const float* __restrict__ sd,
                                __half* __restrict__ sgt, __half* __restrict__ sut,
                                __half* __restrict__ sdt) {
    int z = blockIdx.z;
    const float* src; __half* dst; int K, N;
    if (z == 0)      { src = sg; dst = sgt; K = HD; N = ID; }
    else if (z == 1) { src = su; dst = sut; K = HD; N = ID; }
    else             { src = sd; dst = sdt; K = ID; N = HD; }
    int tn = N / 32;
    int n0 = (blockIdx.x % tn) * 32, k0 = (blockIdx.x / tn) * 32;
    tr_tile(src, dst, K, N, k0, n0);
}

// ---------------- GEMM 1: act = silu(X@Wg) * (X@Wu)  [fp16 MMA] ----------------
// BM=128, BN=64 i-cols (gate+up), BK=32. 8 warps (2M x 4N); warp tile 64x16 per matrix.
// 2 CTAs/SM. z<8: routed expert z; z==8: shared expert.
__global__ __launch_bounds__(256, 2)
void gemm1_mma(const __half* __restrict__ Xh,
               const __half* __restrict__ Wgt_base,
               const __half* __restrict__ Wut_base,
               const __half* __restrict__ Sgt,
               const __half* __restrict__ Sut,
               __half* __restrict__ ActR,
               __half* __restrict__ ActS) {
    int e = blockIdx.z;
    int n; const __half *Wg, *Wu; __half* Act; int routed = (e < ED);
    if (routed) { n = g_cnt[e]; Wg = Wgt_base + (size_t)e * HD * ID; Wu = Wut_base + (size_t)e * HD * ID; Act = ActR; }
    else        { n = TT;       Wg = Sgt;                             Wu = Sut;                             Act = ActS; }
    int row0 = blockIdx.y * 128;
    if (row0 >= n) return;
    int col0 = blockIdx.x * 64;

    extern __shared__ __align__(16) char dyn[];
    uint32_t smem = smem_u32(dyn);
    __shared__ int s_tok[128], s_orow[128];

    int tid = threadIdx.x;
    if (tid < 128) {
        int r = row0 + tid;
        int t, o;
        if (routed) { t = (r < n) ? g_tok[e][r] : g_tok[e][0];
                      o = (r < n) ? g_slot[e][r] : 0; }
        else        { t = (r < n) ? r : 0; o = t; }
        s_tok[tid] = t; s_orow[tid] = o;
    }
    __syncthreads();

    int w = tid >> 5, lane = tid & 31;
    int wm = (w >> 2) * 64, wn = (w & 3) * 16;
    int gi = lane >> 2, tig = lane & 3;
    int l15 = lane & 15, l16 = lane >> 4;

    float cg[4][2][4], cu[4][2][4];
#pragma unroll
    for (int mt = 0; mt < 4; mt++)
#pragma unroll
        for (int nt = 0; nt < 2; nt++)
#pragma unroll
            for (int i = 0; i < 4; i++) { cg[mt][nt][i] = 0.f; cu[mt][nt][i] = 0.f; }

    auto issue = [&](int c) {
        uint32_t base = smem + (c & (NSTAGE - 1)) * STAGE1;
        uint32_t As = base, Bg_s = base + 8192, Bu_s = base + 12288;
        int k0 = c * 32;
        // A: 128 rows x 32 fp16 (64B rows) -> 2 loads/thread
#pragma unroll
        for (int it = 0; it < 2; it++) {
            int i = tid + it * 256; int r = i >> 2, q = i & 3;
            CP_ASYNC16(As + swz(r, q), Xh + (size_t)s_tok[r] * HD + k0 + q * 8);
        }
        // Bg/Bu: 64 rows x 32 fp16 each -> 1+1 loads/thread
        {
            int r = tid >> 2, q = tid & 3;
            uint32_t d = swz(r, q);
            CP_ASYNC16(Bg_s + d, Wg + (size_t)(col0 + r) * HD + k0 + q * 8);
            CP_ASYNC16(Bu_s + d, Wu + (size_t)(col0 + r) * HD + k0 + q * 8);
        }
    };
    auto compute = [&](uint32_t base) {
        uint32_t As = base, Bg_s = base + 8192, Bu_s = base + 12288;
#pragma unroll
        for (int s = 0; s < 2; s++) {
            int c = s * 2 + l16;
            uint32_t a[4][4], bg[4], bu[4];
#pragma unroll
            for (int mt = 0; mt < 4; mt++) {
                int row = wm + mt * 16 + l15;
                LDSM_X4(a[mt][0], a[mt][1], a[mt][2], a[mt][3], As + swz(row, c));
            }
            {
                int row = wn + l15;
                uint32_t off = swz(row, c);
                LDSM_X4(bg[0], bg[1], bg[2], bg[3], Bg_s + off);
                LDSM_X4(bu[0], bu[1], bu[2], bu[3], Bu_s + off);
            }
#pragma unroll
            for (int mt = 0; mt < 4; mt++) {
                MMA16(cg[mt][0], a[mt], bg[0], bg[2]);
                MMA16(cg[mt][1], a[mt], bg[1], bg[3]);
                MMA16(cu[mt][0], a[mt], bu[0], bu[2]);
                MMA16(cu[mt][1], a[mt], bu[1], bu[3]);
            }
        }
    };

    const int NCH = HD / 32;  // 32
    issue(0); CP_COMMIT();
    issue(1); CP_COMMIT();
    issue(2); CP_COMMIT();
    for (int c = 0; c < NCH; c++) {
        CP_WAIT2();
        __syncthreads();
        if (c + 3 < NCH) issue(c + 3);
        CP_COMMIT();
        compute(smem + (c & (NSTAGE - 1)) * STAGE1);
    }

    // epilogue: silu(g)*u, fp16 stores to gathered rows
#pragma unroll
    for (int mt = 0; mt < 4; mt++)
#pragma unroll
        for (int nt = 0; nt < 2; nt++) {
            int col = col0 + wn + nt * 8 + tig * 2;
#pragma unroll
            for (int h = 0; h < 2; h++) {
                int lr = wm + mt * 16 + gi + h * 8;
                if (row0 + lr < n) {
                    float g0 = cg[mt][nt][h * 2], g1 = cg[mt][nt][h * 2 + 1];
                    float u0 = cu[mt][nt][h * 2], u1 = cu[mt][nt][h * 2 + 1];
                    float o0 = g0 / (1.f + expf(-g0)) * u0;
                    float o1 = g1 / (1.f + expf(-g1)) * u1;
                    *(__half2*)(Act + (size_t)s_orow[lr] * ID + col) =
                        __floats2half2_rn(o0, o1);
                }
            }
        }
}

// ---------------- GEMM 2: Out = Act @ Wd  [fp16 MMA] ----------------
// BM=256, BN=128, BK=32. 8 warps (4M x 2N); warp tile 64x64.
__global__ __launch_bounds__(256, 1)
void gemm2_mma(const __half* __restrict__ ActR,
               const __half* __restrict__ ActS,
               const __half* __restrict__ Wdt_base,
               const __half* __restrict__ Sdt,
               float* __restrict__ OutR,
               float* __restrict__ OutS) {
    int e = blockIdx.z;
    int n; const __half *Wd, *Src; float* Out; int routed = (e < ED);
    if (routed) { n = g_cnt[e]; Wd = Wdt_base + (size_t)e * ID * HD; Src = ActR; Out = OutR; }
    else        { n = TT;       Wd = Sdt;                             Src = ActS; Out = OutS; }
    int row0 = blockIdx.y * 256;
    if (row0 >= n) return;
    int col0 = blockIdx.x * 128;

    extern __shared__ __align__(16) char dyn[];
    uint32_t smem = smem_u32(dyn);
    __shared__ int s_row[256];

    int tid = threadIdx.x;
    {
        int r = row0 + tid;
        int a;
        if (routed) a = (r < n) ? g_slot[e][r] : 0;
        else        a = (r < n) ? r : 0;
        s_row[tid] = a;
    }
    __syncthreads();

    int w = tid >> 5, lane = tid & 31;
    int wm = (w >> 1) * 64, wn = (w & 1) * 64;
    int gi = lane >> 2, tig = lane & 3;
    int l15 = lane & 15, l16 = lane >> 4;

    float cc[4][8][4];
#pragma unroll
    for (int mt = 0; mt < 4; mt++)
#pragma unroll
        for (int nt = 0; nt < 8; nt++)
#pragma unroll
            for (int i = 0; i < 4; i++) cc[mt][nt][i] = 0.f;

    auto issue = [&](int c) {
        uint32_t base = smem + (c & (NSTAGE - 1)) * STAGE2;
        uint32_t As = base, Bs = base + 16384;
        int k0 = c * 32;
#pragma unroll
        for (int it = 0; it < 4; it++) {
            int i = tid + it * 256; int r = i >> 2, q = i & 3;
            CP_ASYNC16(As + swz(r, q), Src + (size_t)s_row[r] * ID + k0 + q * 8);
        }
#pragma unroll
        for (int it = 0; it < 2; it++) {
            int i = tid + it * 256; int r = i >> 2, q = i & 3;
            CP_ASYNC16(Bs + swz(r, q), Wd + (size_t)(col0 + r) * ID + k0 + q * 8);
        }
    };
    auto compute = [&](uint32_t base) {
        uint32_t As = base, Bs = base + 16384;
#pragma unroll
        for (int s = 0; s < 2; s++) {
            int c = s * 2 + l16;
            uint32_t a[4][4], b[4][4];
#pragma unroll
            for (int mt = 0; mt < 4; mt++) {
                int row = wm + mt * 16 + l15;
                LDSM_X4(a[mt][0], a[mt][1], a[mt][2], a[mt][3], As + swz(row, c));
            }
#pragma unroll
            for (int p = 0; p < 4; p++) {
                int row = wn + p * 16 + l15;
                LDSM_X4(b[p][0], b[p][1], b[p][2], b[p][3], Bs + swz(row, c));
            }
#pragma unroll
            for (int mt = 0; mt < 4; mt++)
#pragma unroll
                for (int p = 0; p < 4; p++) {
                    MMA16(cc[mt][2 * p],     a[mt], b[p][0], b[p][2]);
                    MMA16(cc[mt][2 * p + 1], a[mt], b[p][1], b[p][3]);
                }
        }
    };

    const int NCH = ID / 32;  // 86
    issue(0); CP_COMMIT();
    issue(1); CP_COMMIT();
    issue(2); CP_COMMIT();
    for (int c = 0; c < NCH; c++) {
        CP_WAIT2();
        __syncthreads();
        if (c + 3 < NCH) issue(c + 3);
        CP_COMMIT();
        compute(smem + (c & (NSTAGE - 1)) * STAGE2);
    }

#pragma unroll
    for (int mt = 0; mt < 4; mt++)
#pragma unroll
        for (int nt = 0; nt < 8; nt++) {
            int col = col0 + wn + nt * 8 + tig * 2;
#pragma unroll
            for (int h = 0; h < 2; h++) {
                int lr = wm + mt * 16 + gi + h * 8;
                if (row0 + lr < n) {
                    float2 o;
                    o.x = cc[mt][nt][h * 2];
                    o.y = cc[mt][nt][h * 2 + 1];
                    *(float2*)(Out + (size_t)s_row[lr] * HD + col) = o;
                }
            }
        }
}

// out[t] += w0*outk[2t] + w1*outk[2t+1]
__global__ void combine_kernel(float* __restrict__ out) {
    int t = blockIdx.x;
    int h = threadIdx.x;
    float w0 = g_wslot[2 * t];
    float w1 = g_wslot[2 * t + 1];
    size_t base = (size_t)(2 * t) * HD + h;
    float v = out[(size_t)t * HD + h];
    v += w0 * g_outk[base] + w1 * g_outk[base + HD];
    out[(size_t)t * HD + h] = v;
}

// ---------------- launch ----------------
extern "C" void kernel_launch(void* const* d_in, const int* in_sizes, int n_in,
                              void* d_out, int out_size) {
    const float* x  = (const float*)d_in[0];
    const float* gw = (const float*)d_in[1];
    const float* wg = (const float*)d_in[2];
    const float* wu = (const float*)d_in[3];
    const float* wd = (const float*)d_in[4];
    const float* sg = (const float*)d_in[5];
    const float* su = (const float*)d_in[6];
    const float* sd = (const float*)d_in[7];
    float* out = (float*)d_out;

    const int SMEM1 = NSTAGE * STAGE1;  // 64KB
    const int SMEM2 = NSTAGE * STAGE2;  // 96KB
    cudaFuncSetAttribute(gemm1_mma, cudaFuncAttributeMaxDynamicSharedMemorySize, SMEM1);
    cudaFuncSetAttribute(gemm2_mma, cudaFuncAttributeMaxDynamicSharedMemorySize, SMEM2);

    __half* xh;  cudaGetSymbolAddress((void**)&xh,  g_xh);
    __half* wgt; cudaGetSymbolAddress((void**)&wgt, g_wgt);
    __half* wut; cudaGetSymbolAddress((void**)&wut, g_wut);
    __half* wdt; cudaGetSymbolAddress((void**)&wdt, g_wdt);
    __half* sgt; cudaGetSymbolAddress((void**)&sgt, g_sgt);
    __half* sut; cudaGetSymbolAddress((void**)&sut, g_sut);
    __half* sdt; cudaGetSymbolAddress((void**)&sdt, g_sdt);
    __half* act; cudaGetSymbolAddress((void**)&act, g_act);
    __half* sact;cudaGetSymbolAddress((void**)&sact,g_sact);
    float* outk; cudaGetSymbolAddress((void**)&outk,g_outk);

    // launch order arranged so gemm1_mma is launch #6 (ncu -s 5 -c 1 profiles it)
    transpose_big<<<dim3(2752, 1, 24), 256>>>(wg, wu, wd, wgt, wut, wdt);     // 1
    transpose_small<<<dim3(2752, 1, 3), 256>>>(sg, su, sd, sgt, sut, sdt);    // 2
    zero_cnt_kernel<<<1, 32>>>();                                             // 3
    gate_kernel<<<TT / 8, 256>>>(x, gw);                                      // 4
    convx_kernel<<<TT * HD / 1024, 256>>>(x);                                 // 5

    {
        dim3 g1(ID / 64, TT / 128, ED + 1);     // (43, 64, 9)
        gemm1_mma<<<g1, 256, SMEM1>>>(xh, wgt, wut, sgt, sut, act, sact);     // 6
        dim3 g2(HD / 128, TT / 256, ED + 1);    // (8, 32, 9)
        gemm2_mma<<<g2, 256, SMEM2>>>(act, sact, wdt, sdt, outk, out);        // 7
    }
    combine_kernel<<<TT, HD>>>(out);                                          // 8
}